// round 1
// baseline (speedup 1.0000x reference)
#include <cuda_runtime.h>
#include <cstddef>

#define DIMM   1024
#define NHEADS 16
#define HD     64
#define BB     4
#define SS     2048

// Scratch (no allocation allowed): qkv = 100.7 MB, attn = 33.6 MB
__device__ float g_qkv[(size_t)BB * SS * 3 * DIMM];
__device__ float g_attn[(size_t)BB * SS * DIMM];

__device__ __forceinline__ float ex2f(float x) {
    float r;
    asm("ex2.approx.ftz.f32 %0, %1;" : "=f"(r) : "f"(x));
    return r;
}

// ---------------------------------------------------------------------------
// Register-tiled SGEMM: C[M,N] = A[M,K] @ B[K,N] (+ bias), all row-major.
// BM=BN=128, BK=8, 256 threads, 8x8 per thread. M,N % 128 == 0, K % 8 == 0.
// ---------------------------------------------------------------------------
template <bool BIAS>
__global__ __launch_bounds__(256) void sgemm_kernel(
    const float* __restrict__ A, const float* __restrict__ B,
    const float* __restrict__ bias, float* __restrict__ C,
    int M, int N, int K)
{
    constexpr int BM = 128, BN = 128, BK = 8, TM = 8, TN = 8;
    __shared__ float As[BK][BM];
    __shared__ float Bs[BK][BN];

    const int tid = threadIdx.x;
    const int bx = blockIdx.x, by = blockIdx.y;

    // A tile loader: each thread one float4 along K
    const int arow = tid >> 1;            // 0..127
    const int acol = (tid & 1) * 4;       // 0 or 4
    // B tile loader: each thread one float4 along N
    const int brow = tid >> 5;            // 0..7
    const int bcol = (tid & 31) * 4;

    const float* Ag = A + (size_t)(by * BM + arow) * K + acol;
    const float* Bg = B + (size_t)brow * N + bx * BN + bcol;

    const int tx = tid & 15, ty = tid >> 4;
    float acc[TM][TN];
#pragma unroll
    for (int i = 0; i < TM; i++)
#pragma unroll
        for (int j = 0; j < TN; j++) acc[i][j] = 0.f;

    for (int k0 = 0; k0 < K; k0 += BK) {
        float4 av = *(const float4*)(Ag + k0);
        float4 bv = *(const float4*)(Bg + (size_t)k0 * N);
        As[acol + 0][arow] = av.x;
        As[acol + 1][arow] = av.y;
        As[acol + 2][arow] = av.z;
        As[acol + 3][arow] = av.w;
        *(float4*)&Bs[brow][bcol] = bv;
        __syncthreads();

#pragma unroll
        for (int k = 0; k < BK; k++) {
            float a[TM], b[TN];
#pragma unroll
            for (int i = 0; i < TM; i++) a[i] = As[k][ty * TM + i];
#pragma unroll
            for (int j = 0; j < TN; j++) b[j] = Bs[k][tx * TN + j];
#pragma unroll
            for (int i = 0; i < TM; i++)
#pragma unroll
                for (int j = 0; j < TN; j++) acc[i][j] += a[i] * b[j];
        }
        __syncthreads();
    }

#pragma unroll
    for (int i = 0; i < TM; i++) {
        const int row = by * BM + ty * TM + i;
#pragma unroll
        for (int j = 0; j < TN; j += 4) {
            const int col = bx * BN + tx * TN + j;
            float4 v = make_float4(acc[i][j], acc[i][j + 1], acc[i][j + 2], acc[i][j + 3]);
            if (BIAS) {
                v.x += bias[col + 0];
                v.y += bias[col + 1];
                v.z += bias[col + 2];
                v.w += bias[col + 3];
            }
            *(float4*)&C[(size_t)row * N + col] = v;
        }
    }
}

// ---------------------------------------------------------------------------
// Flash attention, fp32. One thread = one query row. 128 q-rows per CTA.
// K/V tiles of 32 rows in smem; all inner-loop smem reads are warp-uniform
// (broadcast). Softmax in base-2 units; scale*log2e folded into Q registers.
// Output written with the reference's no-transpose reshape permutation:
//   O[b,h,s,d] -> g_attn[b][h*128 + s/16][(s%16)*64 + d]
// ---------------------------------------------------------------------------
__global__ __launch_bounds__(128, 1) void flash_kernel()
{
    __shared__ float Ks[32][64];
    __shared__ float Vs[32][64];

    const int t  = threadIdx.x;
    const int qt = blockIdx.x;   // 0..15
    const int h  = blockIdx.y;   // 0..15
    const int b  = blockIdx.z;   // 0..3
    const int sq = qt * 128 + t;

    const float scale2 = 0.125f * 1.44269504088896340736f; // (1/sqrt(64)) * log2(e)

    const float* qg = g_qkv + ((size_t)(b * SS + sq)) * (3 * DIMM) + h * HD;
    float q[64], o[64];
#pragma unroll
    for (int d = 0; d < 64; d += 4) {
        float4 v = *(const float4*)(qg + d);
        q[d]     = v.x * scale2;
        q[d + 1] = v.y * scale2;
        q[d + 2] = v.z * scale2;
        q[d + 3] = v.w * scale2;
    }
#pragma unroll
    for (int d = 0; d < 64; d++) o[d] = 0.f;

    float m2 = -1e30f, l = 0.f;

    const float* kbase = g_qkv + (size_t)b * SS * (3 * DIMM) + DIMM + h * HD;

    for (int kt = 0; kt < 64; kt++) {
        __syncthreads();
#pragma unroll
        for (int f = t; f < 512; f += 128) {
            const int j = f >> 4, c = (f & 15) * 4;
            const float* src = kbase + (size_t)(kt * 32 + j) * (3 * DIMM) + c;
            *(float4*)&Ks[j][c] = *(const float4*)src;
            *(float4*)&Vs[j][c] = *(const float4*)(src + DIMM);
        }
        __syncthreads();

        float s[32];
#pragma unroll
        for (int j = 0; j < 32; j++) {
            float acc = 0.f;
#pragma unroll
            for (int d = 0; d < 64; d += 4) {
                float4 kv = *(const float4*)&Ks[j][d];
                acc += q[d] * kv.x;
                acc += q[d + 1] * kv.y;
                acc += q[d + 2] * kv.z;
                acc += q[d + 3] * kv.w;
            }
            s[j] = acc;  // already in log2 units
        }

        float mt = m2;
#pragma unroll
        for (int j = 0; j < 32; j++) mt = fmaxf(mt, s[j]);

        const float corr = ex2f(m2 - mt);
        m2 = mt;
        l *= corr;
#pragma unroll
        for (int j = 0; j < 32; j++) {
            s[j] = ex2f(s[j] - mt);   // p_j
            l += s[j];
        }

#pragma unroll
        for (int d = 0; d < 64; d += 4) {
            float a0 = o[d] * corr, a1 = o[d + 1] * corr;
            float a2 = o[d + 2] * corr, a3 = o[d + 3] * corr;
#pragma unroll
            for (int j = 0; j < 32; j++) {
                float4 v = *(const float4*)&Vs[j][d];
                a0 += s[j] * v.x;
                a1 += s[j] * v.y;
                a2 += s[j] * v.z;
                a3 += s[j] * v.w;
            }
            o[d] = a0; o[d + 1] = a1; o[d + 2] = a2; o[d + 3] = a3;
        }
    }

    const float inv = 1.f / l;
    float* dst = g_attn + ((size_t)b * SS + h * 128 + (sq >> 4)) * DIMM + (sq & 15) * 64;
#pragma unroll
    for (int d = 0; d < 64; d += 4) {
        float4 v = make_float4(o[d] * inv, o[d + 1] * inv, o[d + 2] * inv, o[d + 3] * inv);
        *(float4*)(dst + d) = v;
    }
}

// ---------------------------------------------------------------------------
// Launch
// ---------------------------------------------------------------------------
extern "C" void kernel_launch(void* const* d_in, const int* in_sizes, int n_in,
                              void* d_out, int out_size)
{
    const float* x     = (const float*)d_in[0];   // [4,2048,1024]
    const float* w_qkv = (const float*)d_in[1];   // [1024,3072]
    const float* w_out = (const float*)d_in[2];   // [1024,1024]
    const float* b_out = (const float*)d_in[3];   // [1024]
    float* out = (float*)d_out;                   // [4,2048,1024]

    float* qkv = nullptr;
    float* attn = nullptr;
    cudaGetSymbolAddress((void**)&qkv, g_qkv);
    cudaGetSymbolAddress((void**)&attn, g_attn);

    const int M = BB * SS;           // 8192

    // 1) QKV projection: [8192,1024] @ [1024,3072]
    {
        dim3 grid((3 * DIMM) / 128, M / 128);
        sgemm_kernel<false><<<grid, 256>>>(x, w_qkv, nullptr, qkv, M, 3 * DIMM, DIMM);
    }

    // 2) Flash attention (writes permuted layout into g_attn)
    {
        dim3 grid(SS / 128, NHEADS, BB);
        flash_kernel<<<grid, 128>>>();
    }

    // 3) Output projection + bias: [8192,1024] @ [1024,1024] + b
    {
        dim3 grid(DIMM / 128, M / 128);
        sgemm_kernel<true><<<grid, 256>>>(attn, w_out, b_out, out, M, DIMM, DIMM);
    }
}

// round 2
// speedup vs baseline: 1.1440x; 1.1440x over previous
#include <cuda_runtime.h>
#include <cstddef>

#define DIMM   1024
#define NHEADS 16
#define HD     64
#define BB     4
#define SS     2048

typedef unsigned long long ull;

// Scratch (no allocation allowed): qkv = 100.7 MB, attn = 33.6 MB
__device__ float g_qkv[(size_t)BB * SS * 3 * DIMM];
__device__ float g_attn[(size_t)BB * SS * DIMM];

__device__ __forceinline__ float ex2f(float x) {
    float r;
    asm("ex2.approx.ftz.f32 %0, %1;" : "=f"(r) : "f"(x));
    return r;
}

// ---- packed f32x2 helpers (Blackwell FFMA2 path; bit-exact vs 2x scalar fma) ----
__device__ __forceinline__ ull pack2(float lo, float hi) {
    ull r;
    asm("mov.b64 %0, {%1, %2};" : "=l"(r) : "f"(lo), "f"(hi));
    return r;
}
__device__ __forceinline__ void unpack2(ull v, float& lo, float& hi) {
    asm("mov.b64 {%0, %1}, %2;" : "=f"(lo), "=f"(hi) : "l"(v));
}
__device__ __forceinline__ ull fma2(ull a, ull b, ull c) {
    ull d;
    asm("fma.rn.f32x2 %0, %1, %2, %3;" : "=l"(d) : "l"(a), "l"(b), "l"(c));
    return d;
}
__device__ __forceinline__ ull mul2(ull a, ull b) {
    ull d;
    asm("mul.rn.f32x2 %0, %1, %2;" : "=l"(d) : "l"(a), "l"(b));
    return d;
}

// ---------------------------------------------------------------------------
// Register-tiled SGEMM with packed f32x2 inner loop.
// C[M,N] = A[M,K] @ B[K,N] (+ bias), row-major. BM=BN=128, BK=8, 256 thr,
// 8x8 per thread held as 8x4 packed pairs.
// ---------------------------------------------------------------------------
template <bool BIAS>
__global__ __launch_bounds__(256) void sgemm_kernel(
    const float* __restrict__ A, const float* __restrict__ B,
    const float* __restrict__ bias, float* __restrict__ C,
    int M, int N, int K)
{
    constexpr int BM = 128, BN = 128, BK = 8;
    __shared__ float As[BK][BM];
    __shared__ float Bs[BK][BN];

    const int tid = threadIdx.x;
    const int bx = blockIdx.x, by = blockIdx.y;

    const int arow = tid >> 1;            // 0..127
    const int acol = (tid & 1) * 4;       // 0 or 4
    const int brow = tid >> 5;            // 0..7
    const int bcol = (tid & 31) * 4;

    const float* Ag = A + (size_t)(by * BM + arow) * K + acol;
    const float* Bg = B + (size_t)brow * N + bx * BN + bcol;

    const int tx = tid & 15, ty = tid >> 4;

    ull acc[8][4];
#pragma unroll
    for (int i = 0; i < 8; i++)
#pragma unroll
        for (int j = 0; j < 4; j++) acc[i][j] = 0ull;   // packed (0.f, 0.f)

    for (int k0 = 0; k0 < K; k0 += BK) {
        float4 av = *(const float4*)(Ag + k0);
        float4 bv = *(const float4*)(Bg + (size_t)k0 * N);
        As[acol + 0][arow] = av.x;
        As[acol + 1][arow] = av.y;
        As[acol + 2][arow] = av.z;
        As[acol + 3][arow] = av.w;
        *(float4*)&Bs[brow][bcol] = bv;
        __syncthreads();

#pragma unroll
        for (int k = 0; k < BK; k++) {
            const float* ap = &As[k][ty * 8];         // 32B aligned
            float4 a0 = *(const float4*)ap;
            float4 a1 = *(const float4*)(ap + 4);
            ull a2[8];
            a2[0] = pack2(a0.x, a0.x); a2[1] = pack2(a0.y, a0.y);
            a2[2] = pack2(a0.z, a0.z); a2[3] = pack2(a0.w, a0.w);
            a2[4] = pack2(a1.x, a1.x); a2[5] = pack2(a1.y, a1.y);
            a2[6] = pack2(a1.z, a1.z); a2[7] = pack2(a1.w, a1.w);

            const ull* bp = (const ull*)&Bs[k][tx * 8]; // 32B aligned
            ull b2[4];
            b2[0] = bp[0]; b2[1] = bp[1]; b2[2] = bp[2]; b2[3] = bp[3];

#pragma unroll
            for (int i = 0; i < 8; i++)
#pragma unroll
                for (int j = 0; j < 4; j++)
                    acc[i][j] = fma2(a2[i], b2[j], acc[i][j]);
        }
        __syncthreads();
    }

#pragma unroll
    for (int i = 0; i < 8; i++) {
        const int row = by * BM + ty * 8 + i;
        float c[8];
#pragma unroll
        for (int j = 0; j < 4; j++) unpack2(acc[i][j], c[2 * j], c[2 * j + 1]);
#pragma unroll
        for (int j = 0; j < 8; j += 4) {
            const int col = bx * BN + tx * 8 + j;
            float4 v = make_float4(c[j], c[j + 1], c[j + 2], c[j + 3]);
            if (BIAS) {
                v.x += bias[col + 0];
                v.y += bias[col + 1];
                v.z += bias[col + 2];
                v.w += bias[col + 3];
            }
            *(float4*)&C[(size_t)row * N + col] = v;
        }
    }
}

// ---------------------------------------------------------------------------
// Flash attention, fp32 with packed f32x2 math. One thread = one query row.
// 128 q-rows per CTA; K/V tiles of 32 rows in smem (all inner-loop smem reads
// are warp-uniform broadcasts). Softmax in base-2 units; scale*log2e folded
// into Q. Output written with the reference's no-transpose reshape:
//   O[b,h,s,d] -> g_attn[b][h*128 + s/16][(s%16)*64 + d]
// ---------------------------------------------------------------------------
__global__ __launch_bounds__(128) void flash_kernel()
{
    __shared__ float Ks[32][64];
    __shared__ float Vs[32][64];

    const int t  = threadIdx.x;
    const int qt = blockIdx.x;   // 0..15
    const int h  = blockIdx.y;   // 0..15
    const int b  = blockIdx.z;   // 0..3
    const int sq = qt * 128 + t;

    const float scale2 = 0.125f * 1.44269504088896340736f; // (1/sqrt(64))*log2(e)

    const float* qg = g_qkv + ((size_t)(b * SS + sq)) * (3 * DIMM) + h * HD;
    ull q2[32], o2[32];
#pragma unroll
    for (int i = 0; i < 16; i++) {
        float4 v = *(const float4*)(qg + i * 4);
        q2[2 * i]     = pack2(v.x * scale2, v.y * scale2);
        q2[2 * i + 1] = pack2(v.z * scale2, v.w * scale2);
        o2[2 * i]     = 0ull;
        o2[2 * i + 1] = 0ull;
    }

    float m2 = -1e30f, l = 0.f;

    const float* kbase = g_qkv + (size_t)b * SS * (3 * DIMM) + DIMM + h * HD;

    for (int kt = 0; kt < 64; kt++) {
        __syncthreads();
#pragma unroll
        for (int f = t; f < 512; f += 128) {
            const int j = f >> 4, c = (f & 15) * 4;
            const float* src = kbase + (size_t)(kt * 32 + j) * (3 * DIMM) + c;
            *(float4*)&Ks[j][c] = *(const float4*)src;
            *(float4*)&Vs[j][c] = *(const float4*)(src + DIMM);
        }
        __syncthreads();

        float s[32];
#pragma unroll
        for (int j = 0; j < 32; j++) {
            const ull* kp = (const ull*)Ks[j];
            ull acc = 0ull;
#pragma unroll
            for (int d2 = 0; d2 < 32; d2++)
                acc = fma2(q2[d2], kp[d2], acc);
            float lo, hi;
            unpack2(acc, lo, hi);
            s[j] = lo + hi;                 // log2-domain score
        }

        float mt = m2;
#pragma unroll
        for (int j = 0; j < 32; j++) mt = fmaxf(mt, s[j]);

        const float corr = ex2f(m2 - mt);
        m2 = mt;
        l *= corr;
#pragma unroll
        for (int j = 0; j < 32; j++) {
            s[j] = ex2f(s[j] - mt);
            l += s[j];
        }

        const ull corr2 = pack2(corr, corr);
#pragma unroll
        for (int d2 = 0; d2 < 32; d2++) o2[d2] = mul2(o2[d2], corr2);

#pragma unroll
        for (int j = 0; j < 32; j++) {
            const ull sj = pack2(s[j], s[j]);
            const ull* vp = (const ull*)Vs[j];
#pragma unroll
            for (int d2 = 0; d2 < 32; d2++)
                o2[d2] = fma2(sj, vp[d2], o2[d2]);
        }
    }

    const float inv = 1.f / l;
    float* dst = g_attn + ((size_t)b * SS + h * 128 + (sq >> 4)) * DIMM + (sq & 15) * 64;
#pragma unroll
    for (int i = 0; i < 16; i++) {
        float x0, x1, x2, x3;
        unpack2(o2[2 * i], x0, x1);
        unpack2(o2[2 * i + 1], x2, x3);
        float4 v = make_float4(x0 * inv, x1 * inv, x2 * inv, x3 * inv);
        *(float4*)(dst + i * 4) = v;
    }
}

// ---------------------------------------------------------------------------
// Launch
// ---------------------------------------------------------------------------
extern "C" void kernel_launch(void* const* d_in, const int* in_sizes, int n_in,
                              void* d_out, int out_size)
{
    const float* x     = (const float*)d_in[0];   // [4,2048,1024]
    const float* w_qkv = (const float*)d_in[1];   // [1024,3072]
    const float* w_out = (const float*)d_in[2];   // [1024,1024]
    const float* b_out = (const float*)d_in[3];   // [1024]
    float* out = (float*)d_out;                   // [4,2048,1024]

    float* qkv = nullptr;
    float* attn = nullptr;
    cudaGetSymbolAddress((void**)&qkv, g_qkv);
    cudaGetSymbolAddress((void**)&attn, g_attn);

    const int M = BB * SS;           // 8192

    // 1) QKV projection: [8192,1024] @ [1024,3072]
    {
        dim3 grid((3 * DIMM) / 128, M / 128);
        sgemm_kernel<false><<<grid, 256>>>(x, w_qkv, nullptr, qkv, M, 3 * DIMM, DIMM);
    }

    // 2) Flash attention (writes permuted layout into g_attn)
    {
        dim3 grid(SS / 128, NHEADS, BB);
        flash_kernel<<<grid, 128>>>();
    }

    // 3) Output projection + bias: [8192,1024] @ [1024,1024] + b
    {
        dim3 grid(DIMM / 128, M / 128);
        sgemm_kernel<true><<<grid, 256>>>(attn, w_out, b_out, out, M, DIMM, DIMM);
    }
}

// round 5
// speedup vs baseline: 1.4923x; 1.3044x over previous
#include <cuda_runtime.h>
#include <cuda_bf16.h>
#include <cstdint>
#include <cstddef>

#define DIMM   1024
#define NHEADS 16
#define BB     4
#define SS     2048
#define MTOT   (BB * SS)      // 8192
#define NQKV   (3 * DIMM)     // 3072

typedef unsigned long long ull;

// ---------------- scratch (__device__ globals; no allocation) ----------------
__device__ float g_qkv [(size_t)MTOT * NQKV];    // 100.7 MB
__device__ float g_attn[(size_t)MTOT * DIMM];    // 33.6 MB
__device__ __nv_bfloat16 g_xh[(size_t)MTOT * DIMM], g_xl[(size_t)MTOT * DIMM];
__device__ __nv_bfloat16 g_ah[(size_t)MTOT * DIMM], g_al[(size_t)MTOT * DIMM];
__device__ __nv_bfloat16 g_wqh[(size_t)NQKV * DIMM], g_wql[(size_t)NQKV * DIMM]; // [N,K]
__device__ __nv_bfloat16 g_woh[(size_t)DIMM * DIMM], g_wol[(size_t)DIMM * DIMM]; // [N,K]

// ---------------- helpers ----------------
__device__ __forceinline__ float ex2f(float x) {
    float r; asm("ex2.approx.ftz.f32 %0, %1;" : "=f"(r) : "f"(x)); return r;
}
__device__ __forceinline__ ull pack2(float lo, float hi) {
    ull r; asm("mov.b64 %0, {%1, %2};" : "=l"(r) : "f"(lo), "f"(hi)); return r;
}
__device__ __forceinline__ void unpack2(ull v, float& lo, float& hi) {
    asm("mov.b64 {%0, %1}, %2;" : "=f"(lo), "=f"(hi) : "l"(v));
}
__device__ __forceinline__ ull fma2(ull a, ull b, ull c) {
    ull d; asm("fma.rn.f32x2 %0, %1, %2, %3;" : "=l"(d) : "l"(a), "l"(b), "l"(c)); return d;
}
__device__ __forceinline__ ull mul2(ull a, ull b) {
    ull d; asm("mul.rn.f32x2 %0, %1, %2;" : "=l"(d) : "l"(a), "l"(b)); return d;
}
__device__ __forceinline__ uint32_t s2u(const void* p) {
    uint32_t a;
    asm("{ .reg .u64 t; cvta.to.shared.u64 t, %1; cvt.u32.u64 %0, t; }" : "=r"(a) : "l"(p));
    return a;
}

// ---------------------------------------------------------------------------
// Split fp32 -> (bf16 hi, bf16 lo)
// ---------------------------------------------------------------------------
__global__ __launch_bounds__(256) void split_kernel(
    const float* __restrict__ in, __nv_bfloat16* __restrict__ oh,
    __nv_bfloat16* __restrict__ ol, int n4)
{
    int i = blockIdx.x * 256 + threadIdx.x;
    if (i >= n4) return;
    float4 v = ((const float4*)in)[i];
    __nv_bfloat16 h0 = __float2bfloat16(v.x), h1 = __float2bfloat16(v.y);
    __nv_bfloat16 h2 = __float2bfloat16(v.z), h3 = __float2bfloat16(v.w);
    __nv_bfloat16 l0 = __float2bfloat16(v.x - __bfloat162float(h0));
    __nv_bfloat16 l1 = __float2bfloat16(v.y - __bfloat162float(h1));
    __nv_bfloat16 l2 = __float2bfloat16(v.z - __bfloat162float(h2));
    __nv_bfloat16 l3 = __float2bfloat16(v.w - __bfloat162float(h3));
    ((__nv_bfloat162*)oh)[2 * i]     = __nv_bfloat162(h0, h1);
    ((__nv_bfloat162*)oh)[2 * i + 1] = __nv_bfloat162(h2, h3);
    ((__nv_bfloat162*)ol)[2 * i]     = __nv_bfloat162(l0, l1);
    ((__nv_bfloat162*)ol)[2 * i + 1] = __nv_bfloat162(l2, l3);
}

// ---------------------------------------------------------------------------
// Split + transpose: fp32 [K,N] row-major -> bf16 [N,K] row-major (hi/lo)
// ---------------------------------------------------------------------------
__global__ __launch_bounds__(256) void tsplit_kernel(
    const float* __restrict__ in, __nv_bfloat16* __restrict__ oh,
    __nv_bfloat16* __restrict__ ol, int K, int N)
{
    __shared__ float tile[32][33];
    const int bn = blockIdx.x * 32, bk = blockIdx.y * 32;
    const int tx = threadIdx.x & 31, ty = threadIdx.x >> 5;
#pragma unroll
    for (int i = 0; i < 4; i++)
        tile[ty + 8 * i][tx] = in[(size_t)(bk + ty + 8 * i) * N + bn + tx];
    __syncthreads();
#pragma unroll
    for (int i = 0; i < 4; i++) {
        const int n = bn + ty + 8 * i, k = bk + tx;
        float v = tile[tx][ty + 8 * i];
        __nv_bfloat16 h = __float2bfloat16(v);
        oh[(size_t)n * K + k] = h;
        ol[(size_t)n * K + k] = __float2bfloat16(v - __bfloat162float(h));
    }
}

// ---------------------------------------------------------------------------
// HMMA bf16-split GEMM: C[M,N] = (Ah+Al)[M,K] @ (Bh+Bl)[N,K]^T (+bias)
// Extended-K over 3 regions (Ah,Bh),(Al,Bh),(Ah,Bl). 128x128 tile, BK=32,
// 256 threads (8 warps, 2x4), mma.sync.m16n8k16 bf16, cp.async double buffer.
// ---------------------------------------------------------------------------
template <bool BIAS>
__global__ __launch_bounds__(256) void gemm_mma(
    const __nv_bfloat16* __restrict__ Ah, const __nv_bfloat16* __restrict__ Al,
    const __nv_bfloat16* __restrict__ Bh, const __nv_bfloat16* __restrict__ Bl,
    const float* __restrict__ bias, float* __restrict__ C,
    int M, int N, int K)
{
    __shared__ __align__(16) __nv_bfloat16 As[2][128][40]; // 40-elt (80B) row stride
    __shared__ __align__(16) __nv_bfloat16 Bs[2][128][40];

    const int tid = threadIdx.x, lane = tid & 31, wid = tid >> 5;
    const int wr = wid & 1, wc = wid >> 1;      // 2 x 4 warp grid
    const int bx = blockIdx.x, by = blockIdx.y;

    const int KC = K / 32;        // chunks per region
    const int S  = 3 * KC;        // total pipeline stages

    float acc[4][4][4];
#pragma unroll
    for (int m = 0; m < 4; m++)
#pragma unroll
        for (int n = 0; n < 4; n++)
#pragma unroll
            for (int e = 0; e < 4; e++) acc[m][n][e] = 0.f;

    // ldmatrix per-lane base addresses (byte offsets within a buffer)
    const uint32_t a_row = wr * 64 + ((lane >> 3) & 1) * 8 + (lane & 7);
    const uint32_t a_col8 = (lane >> 4) * 8;                  // +8 cols for k-hi lanes
    const uint32_t b_row = wc * 32 + (lane >> 4) * 8 + (lane & 7);
    const uint32_t b_col8 = ((lane >> 3) & 1) * 8;
    const uint32_t abase0 = s2u(&As[0][0][0]) + a_row * 80 + a_col8 * 2;
    const uint32_t bbase0 = s2u(&Bs[0][0][0]) + b_row * 80 + b_col8 * 2;
    const uint32_t BUFSTR = 128 * 40 * 2;   // bytes per buffer

#define ISSUE_LOAD(s_)                                                            \
    {                                                                             \
        const int s__ = (s_);                                                     \
        const int region = s__ / KC;                                              \
        const int k0 = (s__ - region * KC) * 32;                                  \
        const __nv_bfloat16* Ag = (region == 1) ? Al : Ah;                        \
        const __nv_bfloat16* Bg = (region == 2) ? Bl : Bh;                        \
        const int buf = s__ & 1;                                                  \
        _Pragma("unroll")                                                         \
        for (int i = 0; i < 2; i++) {                                             \
            const int chunk = tid + i * 256;                                      \
            const int row = chunk >> 2, seg = chunk & 3;                          \
            uint32_t da = s2u(&As[buf][row][seg * 8]);                            \
            const void* ga = Ag + (size_t)(by * 128 + row) * K + k0 + seg * 8;    \
            asm volatile("cp.async.cg.shared.global [%0], [%1], 16;"              \
                         :: "r"(da), "l"(ga));                                    \
            uint32_t db = s2u(&Bs[buf][row][seg * 8]);                            \
            const void* gb = Bg + (size_t)(bx * 128 + row) * K + k0 + seg * 8;    \
            asm volatile("cp.async.cg.shared.global [%0], [%1], 16;"              \
                         :: "r"(db), "l"(gb));                                    \
        }                                                                         \
        asm volatile("cp.async.commit_group;" ::: "memory");                      \
    }

    ISSUE_LOAD(0);

    for (int s = 0; s < S; s++) {
        if (s + 1 < S) {
            ISSUE_LOAD(s + 1);
            asm volatile("cp.async.wait_group 1;" ::: "memory");
        } else {
            asm volatile("cp.async.wait_group 0;" ::: "memory");
        }
        __syncthreads();

        const uint32_t boff = (s & 1) ? BUFSTR : 0;
        const uint32_t abase = abase0 + boff;
        const uint32_t bbase = bbase0 + boff;

#pragma unroll
        for (int h = 0; h < 2; h++) {
            uint32_t a[4][4], b[4][2];
#pragma unroll
            for (int m = 0; m < 4; m++) {
                uint32_t addr = abase + m * 16 * 80 + h * 32;
                asm volatile("ldmatrix.sync.aligned.m8n8.x4.shared.b16 "
                             "{%0,%1,%2,%3}, [%4];"
                             : "=r"(a[m][0]), "=r"(a[m][1]),
                               "=r"(a[m][2]), "=r"(a[m][3]) : "r"(addr));
            }
#pragma unroll
            for (int p = 0; p < 2; p++) {
                uint32_t addr = bbase + p * 16 * 80 + h * 32;
                uint32_t r0, r1, r2, r3;
                asm volatile("ldmatrix.sync.aligned.m8n8.x4.shared.b16 "
                             "{%0,%1,%2,%3}, [%4];"
                             : "=r"(r0), "=r"(r1), "=r"(r2), "=r"(r3) : "r"(addr));
                b[2 * p][0] = r0; b[2 * p][1] = r1;
                b[2 * p + 1][0] = r2; b[2 * p + 1][1] = r3;
            }
#pragma unroll
            for (int m = 0; m < 4; m++)
#pragma unroll
                for (int n = 0; n < 4; n++)
                    asm volatile(
                        "mma.sync.aligned.m16n8k16.row.col.f32.bf16.bf16.f32 "
                        "{%0,%1,%2,%3}, {%4,%5,%6,%7}, {%8,%9}, {%0,%1,%2,%3};"
                        : "+f"(acc[m][n][0]), "+f"(acc[m][n][1]),
                          "+f"(acc[m][n][2]), "+f"(acc[m][n][3])
                        : "r"(a[m][0]), "r"(a[m][1]), "r"(a[m][2]), "r"(a[m][3]),
                          "r"(b[n][0]), "r"(b[n][1]));
        }
        __syncthreads();
    }
#undef ISSUE_LOAD

    // Epilogue: c0,c1 at (row, col..col+1), c2,c3 at (row+8, same cols)
#pragma unroll
    for (int m = 0; m < 4; m++) {
        const int r0 = by * 128 + wr * 64 + m * 16 + (lane >> 2);
#pragma unroll
        for (int n = 0; n < 4; n++) {
            const int col = bx * 128 + wc * 32 + n * 8 + 2 * (lane & 3);
            float2 v0 = make_float2(acc[m][n][0], acc[m][n][1]);
            float2 v1 = make_float2(acc[m][n][2], acc[m][n][3]);
            if (BIAS) {
                const float b0 = bias[col], b1 = bias[col + 1];
                v0.x += b0; v0.y += b1; v1.x += b0; v1.y += b1;
            }
            *(float2*)&C[(size_t)r0 * N + col] = v0;
            *(float2*)&C[(size_t)(r0 + 8) * N + col] = v1;
        }
    }
}

// ---------------------------------------------------------------------------
// Flash attention (fp32 + FFMA2) — unchanged (issue-floor bound; HMMA port next)
// ---------------------------------------------------------------------------
__global__ __launch_bounds__(128) void flash_kernel()
{
    __shared__ float Ks[32][64];
    __shared__ float Vs[32][64];

    const int t  = threadIdx.x;
    const int qt = blockIdx.x;
    const int h  = blockIdx.y;
    const int b  = blockIdx.z;
    const int sq = qt * 128 + t;

    const float scale2 = 0.125f * 1.44269504088896340736f;

    const float* qg = g_qkv + ((size_t)(b * SS + sq)) * NQKV + h * 64;
    ull q2[32], o2[32];
#pragma unroll
    for (int i = 0; i < 16; i++) {
        float4 v = *(const float4*)(qg + i * 4);
        q2[2 * i]     = pack2(v.x * scale2, v.y * scale2);
        q2[2 * i + 1] = pack2(v.z * scale2, v.w * scale2);
        o2[2 * i] = 0ull; o2[2 * i + 1] = 0ull;
    }

    float m2 = -1e30f, l = 0.f;
    const float* kbase = g_qkv + (size_t)b * SS * NQKV + DIMM + h * 64;

    for (int kt = 0; kt < 64; kt++) {
        __syncthreads();
#pragma unroll
        for (int f = t; f < 512; f += 128) {
            const int j = f >> 4, c = (f & 15) * 4;
            const float* src = kbase + (size_t)(kt * 32 + j) * NQKV + c;
            *(float4*)&Ks[j][c] = *(const float4*)src;
            *(float4*)&Vs[j][c] = *(const float4*)(src + DIMM);
        }
        __syncthreads();

        float s[32];
#pragma unroll
        for (int j = 0; j < 32; j++) {
            const ull* kp = (const ull*)Ks[j];
            ull acc = 0ull;
#pragma unroll
            for (int d2 = 0; d2 < 32; d2++) acc = fma2(q2[d2], kp[d2], acc);
            float lo, hi; unpack2(acc, lo, hi);
            s[j] = lo + hi;
        }

        float mt = m2;
#pragma unroll
        for (int j = 0; j < 32; j++) mt = fmaxf(mt, s[j]);
        const float corr = ex2f(m2 - mt);
        m2 = mt; l *= corr;
#pragma unroll
        for (int j = 0; j < 32; j++) { s[j] = ex2f(s[j] - mt); l += s[j]; }

        const ull corr2 = pack2(corr, corr);
#pragma unroll
        for (int d2 = 0; d2 < 32; d2++) o2[d2] = mul2(o2[d2], corr2);
#pragma unroll
        for (int j = 0; j < 32; j++) {
            const ull sj = pack2(s[j], s[j]);
            const ull* vp = (const ull*)Vs[j];
#pragma unroll
            for (int d2 = 0; d2 < 32; d2++) o2[d2] = fma2(sj, vp[d2], o2[d2]);
        }
    }

    const float inv = 1.f / l;
    float* dst = g_attn + ((size_t)b * SS + h * 128 + (sq >> 4)) * DIMM + (sq & 15) * 64;
#pragma unroll
    for (int i = 0; i < 16; i++) {
        float x0, x1, x2, x3;
        unpack2(o2[2 * i], x0, x1);
        unpack2(o2[2 * i + 1], x2, x3);
        float4 v = make_float4(x0 * inv, x1 * inv, x2 * inv, x3 * inv);
        *(float4*)(dst + i * 4) = v;
    }
}

// ---------------------------------------------------------------------------
// Launch
// ---------------------------------------------------------------------------
extern "C" void kernel_launch(void* const* d_in, const int* in_sizes, int n_in,
                              void* d_out, int out_size)
{
    const float* x     = (const float*)d_in[0];
    const float* w_qkv = (const float*)d_in[1];   // [1024,3072] = [K,N]
    const float* w_out = (const float*)d_in[2];   // [1024,1024]
    const float* b_out = (const float*)d_in[3];
    float* out = (float*)d_out;

    float *qkv, *attn;
    __nv_bfloat16 *xh, *xl, *ah, *al, *wqh, *wql, *woh, *wol;
    cudaGetSymbolAddress((void**)&qkv,  g_qkv);
    cudaGetSymbolAddress((void**)&attn, g_attn);
    cudaGetSymbolAddress((void**)&xh,  g_xh);  cudaGetSymbolAddress((void**)&xl,  g_xl);
    cudaGetSymbolAddress((void**)&ah,  g_ah);  cudaGetSymbolAddress((void**)&al,  g_al);
    cudaGetSymbolAddress((void**)&wqh, g_wqh); cudaGetSymbolAddress((void**)&wql, g_wql);
    cudaGetSymbolAddress((void**)&woh, g_woh); cudaGetSymbolAddress((void**)&wol, g_wol);

    // 1) split x ; split+transpose w_qkv
    {
        const int n4 = MTOT * DIMM / 4;
        split_kernel<<<n4 / 256, 256>>>(x, xh, xl, n4);
        tsplit_kernel<<<dim3(NQKV / 32, DIMM / 32), 256>>>(w_qkv, wqh, wql, DIMM, NQKV);
    }
    // 2) QKV = x @ w_qkv (HMMA bf16-split)
    gemm_mma<false><<<dim3(NQKV / 128, MTOT / 128), 256>>>(
        xh, xl, wqh, wql, nullptr, qkv, MTOT, NQKV, DIMM);

    // 3) attention
    flash_kernel<<<dim3(SS / 128, NHEADS, BB), 128>>>();

    // 4) split attn ; split+transpose w_out
    {
        const int n4 = MTOT * DIMM / 4;
        split_kernel<<<n4 / 256, 256>>>(attn, ah, al, n4);
        tsplit_kernel<<<dim3(DIMM / 32, DIMM / 32), 256>>>(w_out, woh, wol, DIMM, DIMM);
    }
    // 5) out = attn @ w_out + b  (HMMA bf16-split)
    gemm_mma<true><<<dim3(DIMM / 128, MTOT / 128), 256>>>(
        ah, al, woh, wol, b_out, out, MTOT, DIMM, DIMM);
}

// round 6
// speedup vs baseline: 3.1834x; 2.1333x over previous
#include <cuda_runtime.h>
#include <cuda_bf16.h>
#include <cstdint>
#include <cstddef>

#define DIMM   1024
#define NHEADS 16
#define HD     64
#define BB     4
#define SS     2048
#define MTOT   (BB * SS)      // 8192
#define NQKV   (3 * DIMM)     // 3072

typedef unsigned long long ull;
typedef __nv_bfloat16 bf16;

// ---------------- scratch (__device__ globals; no allocation) ----------------
__device__ float g_qkv [(size_t)MTOT * NQKV];                      // 100.7 MB
__device__ bf16 g_xh[(size_t)MTOT * DIMM], g_xl[(size_t)MTOT * DIMM];
__device__ bf16 g_ah[(size_t)MTOT * DIMM], g_al[(size_t)MTOT * DIMM];
__device__ bf16 g_wqh[(size_t)NQKV * DIMM], g_wql[(size_t)NQKV * DIMM]; // [N,K]
__device__ bf16 g_woh[(size_t)DIMM * DIMM], g_wol[(size_t)DIMM * DIMM]; // [N,K]
// head-major [b,h,s,d] split Q/K/V (Q pre-scaled by 0.125*log2e)
__device__ bf16 g_q2h[(size_t)MTOT * DIMM], g_q2l[(size_t)MTOT * DIMM];
__device__ bf16 g_k2h[(size_t)MTOT * DIMM], g_k2l[(size_t)MTOT * DIMM];
__device__ bf16 g_v2h[(size_t)MTOT * DIMM], g_v2l[(size_t)MTOT * DIMM];

// ---------------- helpers ----------------
__device__ __forceinline__ float ex2f(float x) {
    float r; asm("ex2.approx.ftz.f32 %0, %1;" : "=f"(r) : "f"(x)); return r;
}
__device__ __forceinline__ uint32_t s2u(const void* p) {
    uint32_t a;
    asm("{ .reg .u64 t; cvta.to.shared.u64 t, %1; cvt.u32.u64 %0, t; }" : "=r"(a) : "l"(p));
    return a;
}
__device__ __forceinline__ void mma16816(float* c, const uint32_t* a, const uint32_t* b) {
    asm volatile("mma.sync.aligned.m16n8k16.row.col.f32.bf16.bf16.f32 "
        "{%0,%1,%2,%3}, {%4,%5,%6,%7}, {%8,%9}, {%0,%1,%2,%3};"
        : "+f"(c[0]), "+f"(c[1]), "+f"(c[2]), "+f"(c[3])
        : "r"(a[0]), "r"(a[1]), "r"(a[2]), "r"(a[3]), "r"(b[0]), "r"(b[1]));
}
__device__ __forceinline__ void ldsm4(uint32_t* r, uint32_t addr) {
    asm volatile("ldmatrix.sync.aligned.m8n8.x4.shared.b16 {%0,%1,%2,%3}, [%4];"
        : "=r"(r[0]), "=r"(r[1]), "=r"(r[2]), "=r"(r[3]) : "r"(addr));
}
__device__ __forceinline__ void ldsm4t(uint32_t* r, uint32_t addr) {
    asm volatile("ldmatrix.sync.aligned.m8n8.x4.trans.shared.b16 {%0,%1,%2,%3}, [%4];"
        : "=r"(r[0]), "=r"(r[1]), "=r"(r[2]), "=r"(r[3]) : "r"(addr));
}
// pack {lo, hi} fp32 -> bf16x2 (lo in low half)
__device__ __forceinline__ uint32_t packbf(float lo, float hi) {
    uint32_t r; asm("cvt.rn.bf16x2.f32 %0, %1, %2;" : "=r"(r) : "f"(hi), "f"(lo)); return r;
}
__device__ __forceinline__ float u2f(uint32_t x) { return __uint_as_float(x); }

// ---------------------------------------------------------------------------
// Split fp32 -> (bf16 hi, bf16 lo)
// ---------------------------------------------------------------------------
__global__ __launch_bounds__(256) void split_kernel(
    const float* __restrict__ in, bf16* __restrict__ oh,
    bf16* __restrict__ ol, int n4)
{
    int i = blockIdx.x * 256 + threadIdx.x;
    if (i >= n4) return;
    float4 v = ((const float4*)in)[i];
    bf16 h0 = __float2bfloat16(v.x), h1 = __float2bfloat16(v.y);
    bf16 h2 = __float2bfloat16(v.z), h3 = __float2bfloat16(v.w);
    ((__nv_bfloat162*)oh)[2 * i]     = __nv_bfloat162(h0, h1);
    ((__nv_bfloat162*)oh)[2 * i + 1] = __nv_bfloat162(h2, h3);
    ((__nv_bfloat162*)ol)[2 * i]     = __nv_bfloat162(
        __float2bfloat16(v.x - __bfloat162float(h0)),
        __float2bfloat16(v.y - __bfloat162float(h1)));
    ((__nv_bfloat162*)ol)[2 * i + 1] = __nv_bfloat162(
        __float2bfloat16(v.z - __bfloat162float(h2)),
        __float2bfloat16(v.w - __bfloat162float(h3)));
}

// ---------------------------------------------------------------------------
// Split + transpose: fp32 [K,N] row-major -> bf16 [N,K] row-major (hi/lo)
// ---------------------------------------------------------------------------
__global__ __launch_bounds__(256) void tsplit_kernel(
    const float* __restrict__ in, bf16* __restrict__ oh,
    bf16* __restrict__ ol, int K, int N)
{
    __shared__ float tile[32][33];
    const int bn = blockIdx.x * 32, bk = blockIdx.y * 32;
    const int tx = threadIdx.x & 31, ty = threadIdx.x >> 5;
#pragma unroll
    for (int i = 0; i < 4; i++)
        tile[ty + 8 * i][tx] = in[(size_t)(bk + ty + 8 * i) * N + bn + tx];
    __syncthreads();
#pragma unroll
    for (int i = 0; i < 4; i++) {
        const int n = bn + ty + 8 * i, k = bk + tx;
        float v = tile[tx][ty + 8 * i];
        bf16 h = __float2bfloat16(v);
        oh[(size_t)n * K + k] = h;
        ol[(size_t)n * K + k] = __float2bfloat16(v - __bfloat162float(h));
    }
}

// ---------------------------------------------------------------------------
// split_qkv: g_qkv fp32 [b*S][3*1024] -> head-major bf16 hi/lo [b,h,s,d]
// Q pre-scaled by 0.125*log2(e).
// ---------------------------------------------------------------------------
__device__ __forceinline__ void wsplit4(bf16* oh, bf16* ol, float4 v) {
    bf16 h0 = __float2bfloat16(v.x), h1 = __float2bfloat16(v.y);
    bf16 h2 = __float2bfloat16(v.z), h3 = __float2bfloat16(v.w);
    ((__nv_bfloat162*)oh)[0] = __nv_bfloat162(h0, h1);
    ((__nv_bfloat162*)oh)[1] = __nv_bfloat162(h2, h3);
    ((__nv_bfloat162*)ol)[0] = __nv_bfloat162(
        __float2bfloat16(v.x - __bfloat162float(h0)),
        __float2bfloat16(v.y - __bfloat162float(h1)));
    ((__nv_bfloat162*)ol)[1] = __nv_bfloat162(
        __float2bfloat16(v.z - __bfloat162float(h2)),
        __float2bfloat16(v.w - __bfloat162float(h3)));
}

__global__ __launch_bounds__(256) void split_qkv_kernel()
{
    const int gid = blockIdx.x * 256 + threadIdx.x;   // BB*NHEADS*SS*16
    const int d4 = gid & 15;
    const int s  = (gid >> 4) & (SS - 1);
    const int h  = (gid >> 15) & (NHEADS - 1);
    const int b  = gid >> 19;
    const float* base = g_qkv + (size_t)(b * SS + s) * NQKV + h * HD + d4 * 4;
    const size_t oi = ((size_t)(b * NHEADS + h) * SS + s) * HD + d4 * 4;
    const float cq = 0.125f * 1.44269504088896340736f;
    float4 q = *(const float4*)base;
    float4 k = *(const float4*)(base + DIMM);
    float4 v = *(const float4*)(base + 2 * DIMM);
    q.x *= cq; q.y *= cq; q.z *= cq; q.w *= cq;
    wsplit4(g_q2h + oi, g_q2l + oi, q);
    wsplit4(g_k2h + oi, g_k2l + oi, k);
    wsplit4(g_v2h + oi, g_v2l + oi, v);
}

// ---------------------------------------------------------------------------
// HMMA bf16-split GEMM (validated round 5): C = (Ah+Al)(Bh+Bl)^T (+bias)
// ---------------------------------------------------------------------------
template <bool BIAS>
__global__ __launch_bounds__(256) void gemm_mma(
    const bf16* __restrict__ Ah, const bf16* __restrict__ Al,
    const bf16* __restrict__ Bh, const bf16* __restrict__ Bl,
    const float* __restrict__ bias, float* __restrict__ C,
    int M, int N, int K)
{
    __shared__ __align__(16) bf16 As[2][128][40];
    __shared__ __align__(16) bf16 Bs[2][128][40];

    const int tid = threadIdx.x, lane = tid & 31, wid = tid >> 5;
    const int wr = wid & 1, wc = wid >> 1;
    const int bx = blockIdx.x, by = blockIdx.y;

    const int KC = K / 32;
    const int S  = 3 * KC;

    float acc[4][4][4];
#pragma unroll
    for (int m = 0; m < 4; m++)
#pragma unroll
        for (int n = 0; n < 4; n++)
#pragma unroll
            for (int e = 0; e < 4; e++) acc[m][n][e] = 0.f;

    const uint32_t a_row = wr * 64 + ((lane >> 3) & 1) * 8 + (lane & 7);
    const uint32_t a_col8 = (lane >> 4) * 8;
    const uint32_t b_row = wc * 32 + (lane >> 4) * 8 + (lane & 7);
    const uint32_t b_col8 = ((lane >> 3) & 1) * 8;
    const uint32_t abase0 = s2u(&As[0][0][0]) + a_row * 80 + a_col8 * 2;
    const uint32_t bbase0 = s2u(&Bs[0][0][0]) + b_row * 80 + b_col8 * 2;
    const uint32_t BUFSTR = 128 * 40 * 2;

#define ISSUE_LOAD(s_)                                                            \
    {                                                                             \
        const int s__ = (s_);                                                     \
        const int region = s__ / KC;                                              \
        const int k0 = (s__ - region * KC) * 32;                                  \
        const bf16* Ag = (region == 1) ? Al : Ah;                                 \
        const bf16* Bg = (region == 2) ? Bl : Bh;                                 \
        const int buf = s__ & 1;                                                  \
        _Pragma("unroll")                                                         \
        for (int i = 0; i < 2; i++) {                                             \
            const int chunk = tid + i * 256;                                      \
            const int row = chunk >> 2, seg = chunk & 3;                          \
            uint32_t da = s2u(&As[buf][row][seg * 8]);                            \
            const void* ga = Ag + (size_t)(by * 128 + row) * K + k0 + seg * 8;    \
            asm volatile("cp.async.cg.shared.global [%0], [%1], 16;"              \
                         :: "r"(da), "l"(ga));                                    \
            uint32_t db = s2u(&Bs[buf][row][seg * 8]);                            \
            const void* gb = Bg + (size_t)(bx * 128 + row) * K + k0 + seg * 8;    \
            asm volatile("cp.async.cg.shared.global [%0], [%1], 16;"              \
                         :: "r"(db), "l"(gb));                                    \
        }                                                                         \
        asm volatile("cp.async.commit_group;" ::: "memory");                      \
    }

    ISSUE_LOAD(0);

    for (int s = 0; s < S; s++) {
        if (s + 1 < S) {
            ISSUE_LOAD(s + 1);
            asm volatile("cp.async.wait_group 1;" ::: "memory");
        } else {
            asm volatile("cp.async.wait_group 0;" ::: "memory");
        }
        __syncthreads();

        const uint32_t boff = (s & 1) ? BUFSTR : 0;
        const uint32_t abase = abase0 + boff;
        const uint32_t bbase = bbase0 + boff;

#pragma unroll
        for (int h = 0; h < 2; h++) {
            uint32_t a[4][4], b[4][2];
#pragma unroll
            for (int m = 0; m < 4; m++)
                ldsm4(a[m], abase + m * 16 * 80 + h * 32);
#pragma unroll
            for (int p = 0; p < 2; p++) {
                uint32_t r[4];
                ldsm4(r, bbase + p * 16 * 80 + h * 32);
                b[2 * p][0] = r[0]; b[2 * p][1] = r[1];
                b[2 * p + 1][0] = r[2]; b[2 * p + 1][1] = r[3];
            }
#pragma unroll
            for (int m = 0; m < 4; m++)
#pragma unroll
                for (int n = 0; n < 4; n++)
                    mma16816(acc[m][n], a[m], b[n]);
        }
        __syncthreads();
    }
#undef ISSUE_LOAD

#pragma unroll
    for (int m = 0; m < 4; m++) {
        const int r0 = by * 128 + wr * 64 + m * 16 + (lane >> 2);
#pragma unroll
        for (int n = 0; n < 4; n++) {
            const int col = bx * 128 + wc * 32 + n * 8 + 2 * (lane & 3);
            float2 v0 = make_float2(acc[m][n][0], acc[m][n][1]);
            float2 v1 = make_float2(acc[m][n][2], acc[m][n][3]);
            if (BIAS) {
                const float b0 = bias[col], b1 = bias[col + 1];
                v0.x += b0; v0.y += b1; v1.x += b0; v1.y += b1;
            }
            *(float2*)&C[(size_t)r0 * N + col] = v0;
            *(float2*)&C[(size_t)(r0 + 8) * N + col] = v1;
        }
    }
}

// ---------------------------------------------------------------------------
// HMMA flash attention. CTA = 128 q-rows of one (b,h); 4 warps, 32 q/warp.
// Key-tiles of 64. QK^T = qh*kh + ql*kh + qh*kl; PV = ph*vh + pl*vh + ph*vl.
// K/V hi/lo tiles double-buffered (cp.async) in dynamic smem, 72-elt rows.
// Epilogue writes hi/lo bf16 directly to g_ah/g_al with the reference's
// no-transpose permutation: row = b*S + h*128 + s/16, col = (s%16)*64 + d.
// ---------------------------------------------------------------------------
__global__ __launch_bounds__(128, 2) void flash_mma(
    const bf16* __restrict__ Qh, const bf16* __restrict__ Ql,
    const bf16* __restrict__ Kh, const bf16* __restrict__ Kl,
    const bf16* __restrict__ Vh, const bf16* __restrict__ Vl,
    bf16* __restrict__ Oh, bf16* __restrict__ Ol)
{
    extern __shared__ char sm[];
    const int tid = threadIdx.x, lane = tid & 31, wid = tid >> 5;
    const int qt = blockIdx.x, h = blockIdx.y, b = blockIdx.z;
    const size_t bh = (size_t)(b * NHEADS + h) * SS;
    const uint32_t smb = s2u(sm);

    // Phase 0: Q tile (hi/lo) -> smem -> fragments
    {
        const bf16* q0 = Qh + (bh + qt * 128) * HD;
        const bf16* q1 = Ql + (bh + qt * 128) * HD;
#pragma unroll
        for (int i = 0; i < 8; i++) {
            const int c = tid + i * 128;           // 0..1023
            const int row = c >> 3, seg = c & 7;
            uint32_t d0 = smb + row * 144 + seg * 16;
            const void* s0 = q0 + (size_t)row * HD + seg * 8;
            asm volatile("cp.async.cg.shared.global [%0], [%1], 16;" :: "r"(d0), "l"(s0));
            uint32_t d1 = smb + 18432 + row * 144 + seg * 16;
            const void* s1 = q1 + (size_t)row * HD + seg * 8;
            asm volatile("cp.async.cg.shared.global [%0], [%1], 16;" :: "r"(d1), "l"(s1));
        }
        asm volatile("cp.async.commit_group;" ::: "memory");
        asm volatile("cp.async.wait_group 0;" ::: "memory");
        __syncthreads();
    }
    uint32_t qfh[2][4][4], qfl[2][4][4];
    {
        const uint32_t arow = wid * 32 + ((lane >> 3) & 1) * 8 + (lane & 7);
        const uint32_t acolb = (lane >> 4) * 16;
#pragma unroll
        for (int m = 0; m < 2; m++)
#pragma unroll
            for (int kk = 0; kk < 4; kk++) {
                ldsm4(qfh[m][kk], smb + (arow + m * 16) * 144 + acolb + kk * 32);
                ldsm4(qfl[m][kk], smb + 18432 + (arow + m * 16) * 144 + acolb + kk * 32);
            }
    }
    __syncthreads();   // smem now reusable by KV pipeline

    float o[2][8][4];
#pragma unroll
    for (int m = 0; m < 2; m++)
#pragma unroll
        for (int n = 0; n < 8; n++)
#pragma unroll
            for (int e = 0; e < 4; e++) o[m][n][e] = 0.f;
    float rm[2][2] = {{-1e30f, -1e30f}, {-1e30f, -1e30f}};
    float rl[2][2] = {{0.f, 0.f}, {0.f, 0.f}};

#define ISSUE_KV(t_)                                                              \
    do {                                                                          \
        const int t__ = (t_);                                                     \
        const uint32_t base_ = smb + (t__ & 1) * 36864;                           \
        const size_t off_ = (bh + (size_t)t__ * 64) * HD;                         \
        const bf16* sA[4] = {Kh + off_, Kl + off_, Vh + off_, Vl + off_};         \
        _Pragma("unroll")                                                         \
        for (int a = 0; a < 4; a++) {                                             \
            _Pragma("unroll")                                                     \
            for (int i = 0; i < 4; i++) {                                         \
                const int c = tid + i * 128;                                      \
                const int row = c >> 3, seg = c & 7;                              \
                uint32_t dst = base_ + a * 9216 + row * 144 + seg * 16;           \
                const void* src = sA[a] + (size_t)row * HD + seg * 8;             \
                asm volatile("cp.async.cg.shared.global [%0], [%1], 16;"          \
                             :: "r"(dst), "l"(src));                              \
            }                                                                     \
        }                                                                         \
        asm volatile("cp.async.commit_group;" ::: "memory");                      \
    } while (0)

    ISSUE_KV(0);

    const uint32_t brow = (lane >> 4) * 8 + (lane & 7);
    const uint32_t bcolb = ((lane >> 3) & 1) * 16;
    const uint32_t vrowi = ((lane >> 3) & 1) * 8 + (lane & 7);
    const uint32_t vcoli = (lane >> 4);

    for (int t = 0; t < 32; t++) {
        if (t + 1 < 32) {
            ISSUE_KV(t + 1);
            asm volatile("cp.async.wait_group 1;" ::: "memory");
        } else {
            asm volatile("cp.async.wait_group 0;" ::: "memory");
        }
        __syncthreads();

        const uint32_t base = smb + (t & 1) * 36864;
        const uint32_t KHb = base, KLb = base + 9216;
        const uint32_t VHb = base + 18432, VLb = base + 27648;

        float s[2][8][4];
#pragma unroll
        for (int m = 0; m < 2; m++)
#pragma unroll
            for (int n = 0; n < 8; n++)
#pragma unroll
                for (int e = 0; e < 4; e++) s[m][n][e] = 0.f;

        // ---- QK^T ----
#pragma unroll
        for (int kk = 0; kk < 4; kk++) {
            uint32_t kb[8][2];
#pragma unroll
            for (int p = 0; p < 4; p++) {
                uint32_t r[4];
                ldsm4(r, KHb + (p * 16 + brow) * 144 + bcolb + kk * 32);
                kb[2 * p][0] = r[0]; kb[2 * p][1] = r[1];
                kb[2 * p + 1][0] = r[2]; kb[2 * p + 1][1] = r[3];
            }
#pragma unroll
            for (int m = 0; m < 2; m++)
#pragma unroll
                for (int n = 0; n < 8; n++) {
                    mma16816(s[m][n], qfh[m][kk], kb[n]);
                    mma16816(s[m][n], qfl[m][kk], kb[n]);
                }
#pragma unroll
            for (int p = 0; p < 4; p++) {
                uint32_t r[4];
                ldsm4(r, KLb + (p * 16 + brow) * 144 + bcolb + kk * 32);
                kb[2 * p][0] = r[0]; kb[2 * p][1] = r[1];
                kb[2 * p + 1][0] = r[2]; kb[2 * p + 1][1] = r[3];
            }
#pragma unroll
            for (int m = 0; m < 2; m++)
#pragma unroll
                for (int n = 0; n < 8; n++)
                    mma16816(s[m][n], qfh[m][kk], kb[n]);
        }

        // ---- softmax (log2-domain; Q pre-scaled) ----
#pragma unroll
        for (int m = 0; m < 2; m++)
#pragma unroll
            for (int eh = 0; eh < 2; eh++) {
                float mx = -1e30f;
#pragma unroll
                for (int n = 0; n < 8; n++) {
                    mx = fmaxf(mx, s[m][n][eh * 2]);
                    mx = fmaxf(mx, s[m][n][eh * 2 + 1]);
                }
                mx = fmaxf(mx, __shfl_xor_sync(0xffffffffu, mx, 1));
                mx = fmaxf(mx, __shfl_xor_sync(0xffffffffu, mx, 2));
                const float newm = fmaxf(rm[m][eh], mx);
                const float corr = ex2f(rm[m][eh] - newm);
                rm[m][eh] = newm;
                float sum = 0.f;
#pragma unroll
                for (int n = 0; n < 8; n++) {
                    float p0 = ex2f(s[m][n][eh * 2] - newm);
                    float p1 = ex2f(s[m][n][eh * 2 + 1] - newm);
                    s[m][n][eh * 2] = p0; s[m][n][eh * 2 + 1] = p1;
                    sum += p0 + p1;
                }
                sum += __shfl_xor_sync(0xffffffffu, sum, 1);
                sum += __shfl_xor_sync(0xffffffffu, sum, 2);
                rl[m][eh] = rl[m][eh] * corr + sum;
#pragma unroll
                for (int n = 0; n < 8; n++) {
                    o[m][n][eh * 2] *= corr;
                    o[m][n][eh * 2 + 1] *= corr;
                }
            }

        // ---- PV ----
#pragma unroll
        for (int kk = 0; kk < 4; kk++) {
            uint32_t ph[2][4], pl[2][4];
#pragma unroll
            for (int m = 0; m < 2; m++)
#pragma unroll
                for (int half = 0; half < 2; half++)
#pragma unroll
                    for (int eh = 0; eh < 2; eh++) {
                        const float p0 = s[m][2 * kk + half][eh * 2];
                        const float p1 = s[m][2 * kk + half][eh * 2 + 1];
                        const uint32_t hp = packbf(p0, p1);
                        const float h0 = u2f(hp << 16), h1 = u2f(hp & 0xffff0000u);
                        ph[m][half * 2 + eh] = hp;
                        pl[m][half * 2 + eh] = packbf(p0 - h0, p1 - h1);
                    }

            uint32_t vb[8][2];
#pragma unroll
            for (int g = 0; g < 4; g++) {
                uint32_t r[4];
                ldsm4t(r, VHb + (kk * 16 + vrowi) * 144 + (g * 2 + vcoli) * 16);
                vb[2 * g][0] = r[0]; vb[2 * g][1] = r[1];
                vb[2 * g + 1][0] = r[2]; vb[2 * g + 1][1] = r[3];
            }
#pragma unroll
            for (int m = 0; m < 2; m++)
#pragma unroll
                for (int n = 0; n < 8; n++) {
                    mma16816(o[m][n], ph[m], vb[n]);
                    mma16816(o[m][n], pl[m], vb[n]);
                }
#pragma unroll
            for (int g = 0; g < 4; g++) {
                uint32_t r[4];
                ldsm4t(r, VLb + (kk * 16 + vrowi) * 144 + (g * 2 + vcoli) * 16);
                vb[2 * g][0] = r[0]; vb[2 * g][1] = r[1];
                vb[2 * g + 1][0] = r[2]; vb[2 * g + 1][1] = r[3];
            }
#pragma unroll
            for (int m = 0; m < 2; m++)
#pragma unroll
                for (int n = 0; n < 8; n++)
                    mma16816(o[m][n], ph[m], vb[n]);
        }
        __syncthreads();
    }
#undef ISSUE_KV

    // ---- epilogue: normalize + write hi/lo bf16 with permutation ----
#pragma unroll
    for (int m = 0; m < 2; m++)
#pragma unroll
        for (int eh = 0; eh < 2; eh++) {
            const float inv = 1.f / rl[m][eh];
            const int gs = qt * 128 + wid * 32 + m * 16 + (lane >> 2) + eh * 8;
            const size_t rowbase =
                ((size_t)(b * SS) + h * 128 + (gs >> 4)) * DIMM + (gs & 15) * HD;
#pragma unroll
            for (int n = 0; n < 8; n++) {
                const int d = n * 8 + 2 * (lane & 3);
                const float p0 = o[m][n][eh * 2] * inv;
                const float p1 = o[m][n][eh * 2 + 1] * inv;
                const uint32_t hp = packbf(p0, p1);
                const float h0 = u2f(hp << 16), h1 = u2f(hp & 0xffff0000u);
                const uint32_t lp = packbf(p0 - h0, p1 - h1);
                *(uint32_t*)(Oh + rowbase + d) = hp;
                *(uint32_t*)(Ol + rowbase + d) = lp;
            }
        }
}

// ---------------------------------------------------------------------------
// Launch
// ---------------------------------------------------------------------------
extern "C" void kernel_launch(void* const* d_in, const int* in_sizes, int n_in,
                              void* d_out, int out_size)
{
    const float* x     = (const float*)d_in[0];
    const float* w_qkv = (const float*)d_in[1];   // [1024,3072] = [K,N]
    const float* w_out = (const float*)d_in[2];   // [1024,1024]
    const float* b_out = (const float*)d_in[3];
    float* out = (float*)d_out;

    float* qkv;
    bf16 *xh, *xl, *ah, *al, *wqh, *wql, *woh, *wol;
    bf16 *q2h, *q2l, *k2h, *k2l, *v2h, *v2l;
    cudaGetSymbolAddress((void**)&qkv, g_qkv);
    cudaGetSymbolAddress((void**)&xh, g_xh);   cudaGetSymbolAddress((void**)&xl, g_xl);
    cudaGetSymbolAddress((void**)&ah, g_ah);   cudaGetSymbolAddress((void**)&al, g_al);
    cudaGetSymbolAddress((void**)&wqh, g_wqh); cudaGetSymbolAddress((void**)&wql, g_wql);
    cudaGetSymbolAddress((void**)&woh, g_woh); cudaGetSymbolAddress((void**)&wol, g_wol);
    cudaGetSymbolAddress((void**)&q2h, g_q2h); cudaGetSymbolAddress((void**)&q2l, g_q2l);
    cudaGetSymbolAddress((void**)&k2h, g_k2h); cudaGetSymbolAddress((void**)&k2l, g_k2l);
    cudaGetSymbolAddress((void**)&v2h, g_v2h); cudaGetSymbolAddress((void**)&v2l, g_v2l);

    cudaFuncSetAttribute(flash_mma, cudaFuncAttributeMaxDynamicSharedMemorySize, 73728);

    // 1) split x ; split+transpose w_qkv
    {
        const int n4 = MTOT * DIMM / 4;
        split_kernel<<<n4 / 256, 256>>>(x, xh, xl, n4);
        tsplit_kernel<<<dim3(NQKV / 32, DIMM / 32), 256>>>(w_qkv, wqh, wql, DIMM, NQKV);
    }
    // 2) QKV = x @ w_qkv (HMMA bf16-split)
    gemm_mma<false><<<dim3(NQKV / 128, MTOT / 128), 256>>>(
        xh, xl, wqh, wql, nullptr, qkv, MTOT, NQKV, DIMM);

    // 3) head-major hi/lo split of Q/K/V (Q pre-scaled)
    split_qkv_kernel<<<(BB * NHEADS * SS * 16) / 256, 256>>>();

    // 4) HMMA flash attention -> writes g_ah/g_al directly (permuted)
    flash_mma<<<dim3(SS / 128, NHEADS, BB), 128, 73728>>>(
        q2h, q2l, k2h, k2l, v2h, v2l, ah, al);

    // 5) split+transpose w_out ; out = attn @ w_out + b
    tsplit_kernel<<<dim3(DIMM / 32, DIMM / 32), 256>>>(w_out, woh, wol, DIMM, DIMM);
    gemm_mma<true><<<dim3(DIMM / 128, MTOT / 128), 256>>>(
        ah, al, woh, wol, b_out, out, MTOT, DIMM, DIMM);
}

// round 7
// speedup vs baseline: 3.5658x; 1.1201x over previous
#include <cuda_runtime.h>
#include <cuda_bf16.h>
#include <cstdint>
#include <cstddef>

#define DIMM   1024
#define NHEADS 16
#define HD     64
#define BB     4
#define SS     2048
#define MTOT   (BB * SS)      // 8192
#define NQKV   (3 * DIMM)     // 3072

typedef __nv_bfloat16 bf16;

// ---------------- scratch (__device__ globals; no allocation) ----------------
__device__ bf16 g_xh[(size_t)MTOT * DIMM], g_xl[(size_t)MTOT * DIMM];
__device__ bf16 g_ah[(size_t)MTOT * DIMM], g_al[(size_t)MTOT * DIMM];
__device__ bf16 g_wqh[(size_t)NQKV * DIMM], g_wql[(size_t)NQKV * DIMM]; // [N,K]
__device__ bf16 g_woh[(size_t)DIMM * DIMM], g_wol[(size_t)DIMM * DIMM]; // [N,K]
// head-major [b,h,s,d] split Q/K/V (Q pre-scaled by 0.125*log2e)
__device__ bf16 g_q2h[(size_t)MTOT * DIMM], g_q2l[(size_t)MTOT * DIMM];
__device__ bf16 g_k2h[(size_t)MTOT * DIMM], g_k2l[(size_t)MTOT * DIMM];
__device__ bf16 g_v2h[(size_t)MTOT * DIMM], g_v2l[(size_t)MTOT * DIMM];

// ---------------- helpers ----------------
__device__ __forceinline__ float ex2f(float x) {
    float r; asm("ex2.approx.ftz.f32 %0, %1;" : "=f"(r) : "f"(x)); return r;
}
__device__ __forceinline__ uint32_t s2u(const void* p) {
    uint32_t a;
    asm("{ .reg .u64 t; cvta.to.shared.u64 t, %1; cvt.u32.u64 %0, t; }" : "=r"(a) : "l"(p));
    return a;
}
__device__ __forceinline__ void mma16816(float* c, const uint32_t* a, const uint32_t* b) {
    asm volatile("mma.sync.aligned.m16n8k16.row.col.f32.bf16.bf16.f32 "
        "{%0,%1,%2,%3}, {%4,%5,%6,%7}, {%8,%9}, {%0,%1,%2,%3};"
        : "+f"(c[0]), "+f"(c[1]), "+f"(c[2]), "+f"(c[3])
        : "r"(a[0]), "r"(a[1]), "r"(a[2]), "r"(a[3]), "r"(b[0]), "r"(b[1]));
}
__device__ __forceinline__ void ldsm4(uint32_t* r, uint32_t addr) {
    asm volatile("ldmatrix.sync.aligned.m8n8.x4.shared.b16 {%0,%1,%2,%3}, [%4];"
        : "=r"(r[0]), "=r"(r[1]), "=r"(r[2]), "=r"(r[3]) : "r"(addr));
}
__device__ __forceinline__ void ldsm4t(uint32_t* r, uint32_t addr) {
    asm volatile("ldmatrix.sync.aligned.m8n8.x4.trans.shared.b16 {%0,%1,%2,%3}, [%4];"
        : "=r"(r[0]), "=r"(r[1]), "=r"(r[2]), "=r"(r[3]) : "r"(addr));
}
// pack {lo, hi} fp32 -> bf16x2 (lo in low half)
__device__ __forceinline__ uint32_t packbf(float lo, float hi) {
    uint32_t r; asm("cvt.rn.bf16x2.f32 %0, %1, %2;" : "=r"(r) : "f"(hi), "f"(lo)); return r;
}
__device__ __forceinline__ float u2f(uint32_t x) { return __uint_as_float(x); }

// ---------------------------------------------------------------------------
// Split fp32 -> (bf16 hi, bf16 lo)
// ---------------------------------------------------------------------------
__global__ __launch_bounds__(256) void split_kernel(
    const float* __restrict__ in, bf16* __restrict__ oh,
    bf16* __restrict__ ol, int n4)
{
    int i = blockIdx.x * 256 + threadIdx.x;
    if (i >= n4) return;
    float4 v = ((const float4*)in)[i];
    bf16 h0 = __float2bfloat16(v.x), h1 = __float2bfloat16(v.y);
    bf16 h2 = __float2bfloat16(v.z), h3 = __float2bfloat16(v.w);
    ((__nv_bfloat162*)oh)[2 * i]     = __nv_bfloat162(h0, h1);
    ((__nv_bfloat162*)oh)[2 * i + 1] = __nv_bfloat162(h2, h3);
    ((__nv_bfloat162*)ol)[2 * i]     = __nv_bfloat162(
        __float2bfloat16(v.x - __bfloat162float(h0)),
        __float2bfloat16(v.y - __bfloat162float(h1)));
    ((__nv_bfloat162*)ol)[2 * i + 1] = __nv_bfloat162(
        __float2bfloat16(v.z - __bfloat162float(h2)),
        __float2bfloat16(v.w - __bfloat162float(h3)));
}

// ---------------------------------------------------------------------------
// Split + transpose: fp32 [K,N] row-major -> bf16 [N,K] row-major (hi/lo)
// ---------------------------------------------------------------------------
__global__ __launch_bounds__(256) void tsplit_kernel(
    const float* __restrict__ in, bf16* __restrict__ oh,
    bf16* __restrict__ ol, int K, int N)
{
    __shared__ float tile[32][33];
    const int bn = blockIdx.x * 32, bk = blockIdx.y * 32;
    const int tx = threadIdx.x & 31, ty = threadIdx.x >> 5;
#pragma unroll
    for (int i = 0; i < 4; i++)
        tile[ty + 8 * i][tx] = in[(size_t)(bk + ty + 8 * i) * N + bn + tx];
    __syncthreads();
#pragma unroll
    for (int i = 0; i < 4; i++) {
        const int n = bn + ty + 8 * i, k = bk + tx;
        float v = tile[tx][ty + 8 * i];
        bf16 h = __float2bfloat16(v);
        oh[(size_t)n * K + k] = h;
        ol[(size_t)n * K + k] = __float2bfloat16(v - __bfloat162float(h));
    }
}

// ---------------------------------------------------------------------------
// HMMA bf16-split GEMM: C = (Ah+Al)(Bh+Bl)^T, 128x128 tile, BK=32, 8 warps.
// 4-stage cp.async ring, ONE __syncthreads per stage.
// MODE 0: fp32 C.  MODE 1: fp32 C + bias.  MODE 2: fused QKV hi/lo split
// (head-major [b,h,s,d]; Q pre-scaled by 0.125*log2e).
// Dynamic smem: 4 slots x (A 10240 + B 10240) = 81920 B.
// ---------------------------------------------------------------------------
template <int MODE>
__global__ __launch_bounds__(256) void gemm_mma(
    const bf16* __restrict__ Ah, const bf16* __restrict__ Al,
    const bf16* __restrict__ Bh, const bf16* __restrict__ Bl,
    const float* __restrict__ bias, float* __restrict__ C,
    bf16* __restrict__ Q2h, bf16* __restrict__ Q2l,
    bf16* __restrict__ K2h, bf16* __restrict__ K2l,
    bf16* __restrict__ V2h, bf16* __restrict__ V2l,
    int M, int N, int K)
{
    extern __shared__ char sm[];
    const uint32_t smb = s2u(sm);
    const int tid = threadIdx.x, lane = tid & 31, wid = tid >> 5;
    const int wr = wid & 1, wc = wid >> 1;
    const int bx = blockIdx.x, by = blockIdx.y;

    const int KC = K / 32;
    const int St = 3 * KC;          // total stages (96 for K=1024)

    float acc[4][4][4];
#pragma unroll
    for (int m = 0; m < 4; m++)
#pragma unroll
        for (int n = 0; n < 4; n++)
#pragma unroll
            for (int e = 0; e < 4; e++) acc[m][n][e] = 0.f;

    const uint32_t a_row = wr * 64 + ((lane >> 3) & 1) * 8 + (lane & 7);
    const uint32_t a_col8 = (lane >> 4) * 8;
    const uint32_t b_row = wc * 32 + (lane >> 4) * 8 + (lane & 7);
    const uint32_t b_col8 = ((lane >> 3) & 1) * 8;
    const uint32_t aoff = a_row * 80 + a_col8 * 2;
    const uint32_t boff = 10240 + b_row * 80 + b_col8 * 2;
    const uint32_t SLOT = 20480;

#define ISSUE_LOAD(s_)                                                            \
    {                                                                             \
        const int s__ = (s_);                                                     \
        const int region = s__ / KC;                                              \
        const int k0 = (s__ - region * KC) * 32;                                  \
        const bf16* Ag = (region == 1) ? Al : Ah;                                 \
        const bf16* Bg = (region == 2) ? Bl : Bh;                                 \
        const uint32_t sb = smb + (uint32_t)(s__ & 3) * SLOT;                     \
        _Pragma("unroll")                                                         \
        for (int i = 0; i < 2; i++) {                                             \
            const int chunk = tid + i * 256;                                      \
            const int row = chunk >> 2, seg = chunk & 3;                          \
            uint32_t da = sb + row * 80 + seg * 16;                               \
            const void* ga = Ag + (size_t)(by * 128 + row) * K + k0 + seg * 8;    \
            asm volatile("cp.async.cg.shared.global [%0], [%1], 16;"              \
                         :: "r"(da), "l"(ga));                                    \
            uint32_t db = sb + 10240 + row * 80 + seg * 16;                       \
            const void* gb = Bg + (size_t)(bx * 128 + row) * K + k0 + seg * 8;    \
            asm volatile("cp.async.cg.shared.global [%0], [%1], 16;"              \
                         :: "r"(db), "l"(gb));                                    \
        }                                                                         \
        asm volatile("cp.async.commit_group;" ::: "memory");                      \
    }

    ISSUE_LOAD(0); ISSUE_LOAD(1); ISSUE_LOAD(2);

    for (int s = 0; s < St; s++) {
        const int rem = St - 1 - s;
        if (rem >= 2)      asm volatile("cp.async.wait_group 2;" ::: "memory");
        else if (rem == 1) asm volatile("cp.async.wait_group 1;" ::: "memory");
        else               asm volatile("cp.async.wait_group 0;" ::: "memory");
        __syncthreads();
        if (s + 3 < St) ISSUE_LOAD(s + 3);

        const uint32_t sb = smb + (uint32_t)(s & 3) * SLOT;
        const uint32_t abase = sb + aoff;
        const uint32_t bbase = sb + boff;

#pragma unroll
        for (int h = 0; h < 2; h++) {
            uint32_t a[4][4], b[4][2];
#pragma unroll
            for (int m = 0; m < 4; m++)
                ldsm4(a[m], abase + m * 16 * 80 + h * 32);
#pragma unroll
            for (int p = 0; p < 2; p++) {
                uint32_t r[4];
                ldsm4(r, bbase + p * 16 * 80 + h * 32);
                b[2 * p][0] = r[0]; b[2 * p][1] = r[1];
                b[2 * p + 1][0] = r[2]; b[2 * p + 1][1] = r[3];
            }
#pragma unroll
            for (int m = 0; m < 4; m++)
#pragma unroll
                for (int n = 0; n < 4; n++)
                    mma16816(acc[m][n], a[m], b[n]);
        }
    }
#undef ISSUE_LOAD

    const float cq = 0.125f * 1.44269504088896340736f;
#pragma unroll
    for (int m = 0; m < 4; m++) {
        const int r0 = by * 128 + wr * 64 + m * 16 + (lane >> 2);
#pragma unroll
        for (int n = 0; n < 4; n++) {
            const int col = bx * 128 + wc * 32 + n * 8 + 2 * (lane & 3);
#pragma unroll
            for (int half = 0; half < 2; half++) {
                const int row = r0 + half * 8;
                float vx = acc[m][n][half * 2], vy = acc[m][n][half * 2 + 1];
                if (MODE == 2) {
                    const int region = col >> 10;
                    const int head = (col >> 6) & (NHEADS - 1);
                    const int d = col & (HD - 1);
                    const int b_ = row >> 11, s_ = row & (SS - 1);
                    const size_t oi =
                        ((size_t)(b_ * NHEADS + head) * SS + s_) * HD + d;
                    if (region == 0) { vx *= cq; vy *= cq; }
                    const uint32_t hp = packbf(vx, vy);
                    const uint32_t lp = packbf(vx - u2f(hp << 16),
                                               vy - u2f(hp & 0xffff0000u));
                    bf16* oh = (region == 0) ? Q2h : (region == 1) ? K2h : V2h;
                    bf16* ol = (region == 0) ? Q2l : (region == 1) ? K2l : V2l;
                    *(uint32_t*)(oh + oi) = hp;
                    *(uint32_t*)(ol + oi) = lp;
                } else {
                    float2 v = make_float2(vx, vy);
                    if (MODE == 1) { v.x += bias[col]; v.y += bias[col + 1]; }
                    *(float2*)&C[(size_t)row * N + col] = v;
                }
            }
        }
    }
}

// ---------------------------------------------------------------------------
// HMMA flash attention (validated round 6). CTA = 128 q-rows of one (b,h).
// ---------------------------------------------------------------------------
__global__ __launch_bounds__(128, 2) void flash_mma(
    const bf16* __restrict__ Qh, const bf16* __restrict__ Ql,
    const bf16* __restrict__ Kh, const bf16* __restrict__ Kl,
    const bf16* __restrict__ Vh, const bf16* __restrict__ Vl,
    bf16* __restrict__ Oh, bf16* __restrict__ Ol)
{
    extern __shared__ char sm[];
    const int tid = threadIdx.x, lane = tid & 31, wid = tid >> 5;
    const int qt = blockIdx.x, h = blockIdx.y, b = blockIdx.z;
    const size_t bh = (size_t)(b * NHEADS + h) * SS;
    const uint32_t smb = s2u(sm);

    // Phase 0: Q tile (hi/lo) -> smem -> fragments
    {
        const bf16* q0 = Qh + (bh + qt * 128) * HD;
        const bf16* q1 = Ql + (bh + qt * 128) * HD;
#pragma unroll
        for (int i = 0; i < 8; i++) {
            const int c = tid + i * 128;
            const int row = c >> 3, seg = c & 7;
            uint32_t d0 = smb + row * 144 + seg * 16;
            const void* s0 = q0 + (size_t)row * HD + seg * 8;
            asm volatile("cp.async.cg.shared.global [%0], [%1], 16;" :: "r"(d0), "l"(s0));
            uint32_t d1 = smb + 18432 + row * 144 + seg * 16;
            const void* s1 = q1 + (size_t)row * HD + seg * 8;
            asm volatile("cp.async.cg.shared.global [%0], [%1], 16;" :: "r"(d1), "l"(s1));
        }
        asm volatile("cp.async.commit_group;" ::: "memory");
        asm volatile("cp.async.wait_group 0;" ::: "memory");
        __syncthreads();
    }
    uint32_t qfh[2][4][4], qfl[2][4][4];
    {
        const uint32_t arow = wid * 32 + ((lane >> 3) & 1) * 8 + (lane & 7);
        const uint32_t acolb = (lane >> 4) * 16;
#pragma unroll
        for (int m = 0; m < 2; m++)
#pragma unroll
            for (int kk = 0; kk < 4; kk++) {
                ldsm4(qfh[m][kk], smb + (arow + m * 16) * 144 + acolb + kk * 32);
                ldsm4(qfl[m][kk], smb + 18432 + (arow + m * 16) * 144 + acolb + kk * 32);
            }
    }
    __syncthreads();

    float o[2][8][4];
#pragma unroll
    for (int m = 0; m < 2; m++)
#pragma unroll
        for (int n = 0; n < 8; n++)
#pragma unroll
            for (int e = 0; e < 4; e++) o[m][n][e] = 0.f;
    float rm[2][2] = {{-1e30f, -1e30f}, {-1e30f, -1e30f}};
    float rl[2][2] = {{0.f, 0.f}, {0.f, 0.f}};

#define ISSUE_KV(t_)                                                              \
    do {                                                                          \
        const int t__ = (t_);                                                     \
        const uint32_t base_ = smb + (t__ & 1) * 36864;                           \
        const size_t off_ = (bh + (size_t)t__ * 64) * HD;                         \
        const bf16* sA[4] = {Kh + off_, Kl + off_, Vh + off_, Vl + off_};         \
        _Pragma("unroll")                                                         \
        for (int a = 0; a < 4; a++) {                                             \
            _Pragma("unroll")                                                     \
            for (int i = 0; i < 4; i++) {                                         \
                const int c = tid + i * 128;                                      \
                const int row = c >> 3, seg = c & 7;                              \
                uint32_t dst = base_ + a * 9216 + row * 144 + seg * 16;           \
                const void* src = sA[a] + (size_t)row * HD + seg * 8;             \
                asm volatile("cp.async.cg.shared.global [%0], [%1], 16;"          \
                             :: "r"(dst), "l"(src));                              \
            }                                                                     \
        }                                                                         \
        asm volatile("cp.async.commit_group;" ::: "memory");                      \
    } while (0)

    ISSUE_KV(0);

    const uint32_t brow = (lane >> 4) * 8 + (lane & 7);
    const uint32_t bcolb = ((lane >> 3) & 1) * 16;
    const uint32_t vrowi = ((lane >> 3) & 1) * 8 + (lane & 7);
    const uint32_t vcoli = (lane >> 4);

    for (int t = 0; t < 32; t++) {
        if (t + 1 < 32) {
            ISSUE_KV(t + 1);
            asm volatile("cp.async.wait_group 1;" ::: "memory");
        } else {
            asm volatile("cp.async.wait_group 0;" ::: "memory");
        }
        __syncthreads();

        const uint32_t base = smb + (t & 1) * 36864;
        const uint32_t KHb = base, KLb = base + 9216;
        const uint32_t VHb = base + 18432, VLb = base + 27648;

        float s[2][8][4];
#pragma unroll
        for (int m = 0; m < 2; m++)
#pragma unroll
            for (int n = 0; n < 8; n++)
#pragma unroll
                for (int e = 0; e < 4; e++) s[m][n][e] = 0.f;

        // ---- QK^T ----
#pragma unroll
        for (int kk = 0; kk < 4; kk++) {
            uint32_t kb[8][2];
#pragma unroll
            for (int p = 0; p < 4; p++) {
                uint32_t r[4];
                ldsm4(r, KHb + (p * 16 + brow) * 144 + bcolb + kk * 32);
                kb[2 * p][0] = r[0]; kb[2 * p][1] = r[1];
                kb[2 * p + 1][0] = r[2]; kb[2 * p + 1][1] = r[3];
            }
#pragma unroll
            for (int m = 0; m < 2; m++)
#pragma unroll
                for (int n = 0; n < 8; n++) {
                    mma16816(s[m][n], qfh[m][kk], kb[n]);
                    mma16816(s[m][n], qfl[m][kk], kb[n]);
                }
#pragma unroll
            for (int p = 0; p < 4; p++) {
                uint32_t r[4];
                ldsm4(r, KLb + (p * 16 + brow) * 144 + bcolb + kk * 32);
                kb[2 * p][0] = r[0]; kb[2 * p][1] = r[1];
                kb[2 * p + 1][0] = r[2]; kb[2 * p + 1][1] = r[3];
            }
#pragma unroll
            for (int m = 0; m < 2; m++)
#pragma unroll
                for (int n = 0; n < 8; n++)
                    mma16816(s[m][n], qfh[m][kk], kb[n]);
        }

        // ---- softmax (log2-domain; Q pre-scaled) ----
#pragma unroll
        for (int m = 0; m < 2; m++)
#pragma unroll
            for (int eh = 0; eh < 2; eh++) {
                float mx = -1e30f;
#pragma unroll
                for (int n = 0; n < 8; n++) {
                    mx = fmaxf(mx, s[m][n][eh * 2]);
                    mx = fmaxf(mx, s[m][n][eh * 2 + 1]);
                }
                mx = fmaxf(mx, __shfl_xor_sync(0xffffffffu, mx, 1));
                mx = fmaxf(mx, __shfl_xor_sync(0xffffffffu, mx, 2));
                const float newm = fmaxf(rm[m][eh], mx);
                const float corr = ex2f(rm[m][eh] - newm);
                rm[m][eh] = newm;
                float sum = 0.f;
#pragma unroll
                for (int n = 0; n < 8; n++) {
                    float p0 = ex2f(s[m][n][eh * 2] - newm);
                    float p1 = ex2f(s[m][n][eh * 2 + 1] - newm);
                    s[m][n][eh * 2] = p0; s[m][n][eh * 2 + 1] = p1;
                    sum += p0 + p1;
                }
                sum += __shfl_xor_sync(0xffffffffu, sum, 1);
                sum += __shfl_xor_sync(0xffffffffu, sum, 2);
                rl[m][eh] = rl[m][eh] * corr + sum;
#pragma unroll
                for (int n = 0; n < 8; n++) {
                    o[m][n][eh * 2] *= corr;
                    o[m][n][eh * 2 + 1] *= corr;
                }
            }

        // ---- PV ----
#pragma unroll
        for (int kk = 0; kk < 4; kk++) {
            uint32_t ph[2][4], pl[2][4];
#pragma unroll
            for (int m = 0; m < 2; m++)
#pragma unroll
                for (int half = 0; half < 2; half++)
#pragma unroll
                    for (int eh = 0; eh < 2; eh++) {
                        const float p0 = s[m][2 * kk + half][eh * 2];
                        const float p1 = s[m][2 * kk + half][eh * 2 + 1];
                        const uint32_t hp = packbf(p0, p1);
                        const float h0 = u2f(hp << 16), h1 = u2f(hp & 0xffff0000u);
                        ph[m][half * 2 + eh] = hp;
                        pl[m][half * 2 + eh] = packbf(p0 - h0, p1 - h1);
                    }

            uint32_t vb[8][2];
#pragma unroll
            for (int g = 0; g < 4; g++) {
                uint32_t r[4];
                ldsm4t(r, VHb + (kk * 16 + vrowi) * 144 + (g * 2 + vcoli) * 16);
                vb[2 * g][0] = r[0]; vb[2 * g][1] = r[1];
                vb[2 * g + 1][0] = r[2]; vb[2 * g + 1][1] = r[3];
            }
#pragma unroll
            for (int m = 0; m < 2; m++)
#pragma unroll
                for (int n = 0; n < 8; n++) {
                    mma16816(o[m][n], ph[m], vb[n]);
                    mma16816(o[m][n], pl[m], vb[n]);
                }
#pragma unroll
            for (int g = 0; g < 4; g++) {
                uint32_t r[4];
                ldsm4t(r, VLb + (kk * 16 + vrowi) * 144 + (g * 2 + vcoli) * 16);
                vb[2 * g][0] = r[0]; vb[2 * g][1] = r[1];
                vb[2 * g + 1][0] = r[2]; vb[2 * g + 1][1] = r[3];
            }
#pragma unroll
            for (int m = 0; m < 2; m++)
#pragma unroll
                for (int n = 0; n < 8; n++)
                    mma16816(o[m][n], ph[m], vb[n]);
        }
        __syncthreads();
    }
#undef ISSUE_KV

    // ---- epilogue: normalize + write hi/lo bf16 with permutation ----
#pragma unroll
    for (int m = 0; m < 2; m++)
#pragma unroll
        for (int eh = 0; eh < 2; eh++) {
            const float inv = 1.f / rl[m][eh];
            const int gs = qt * 128 + wid * 32 + m * 16 + (lane >> 2) + eh * 8;
            const size_t rowbase =
                ((size_t)(b * SS) + h * 128 + (gs >> 4)) * DIMM + (gs & 15) * HD;
#pragma unroll
            for (int n = 0; n < 8; n++) {
                const int d = n * 8 + 2 * (lane & 3);
                const float p0 = o[m][n][eh * 2] * inv;
                const float p1 = o[m][n][eh * 2 + 1] * inv;
                const uint32_t hp = packbf(p0, p1);
                const float h0 = u2f(hp << 16), h1 = u2f(hp & 0xffff0000u);
                const uint32_t lp = packbf(p0 - h0, p1 - h1);
                *(uint32_t*)(Oh + rowbase + d) = hp;
                *(uint32_t*)(Ol + rowbase + d) = lp;
            }
        }
}

// ---------------------------------------------------------------------------
// Launch
// ---------------------------------------------------------------------------
extern "C" void kernel_launch(void* const* d_in, const int* in_sizes, int n_in,
                              void* d_out, int out_size)
{
    const float* x     = (const float*)d_in[0];
    const float* w_qkv = (const float*)d_in[1];   // [1024,3072] = [K,N]
    const float* w_out = (const float*)d_in[2];   // [1024,1024]
    const float* b_out = (const float*)d_in[3];
    float* out = (float*)d_out;

    bf16 *xh, *xl, *ah, *al, *wqh, *wql, *woh, *wol;
    bf16 *q2h, *q2l, *k2h, *k2l, *v2h, *v2l;
    cudaGetSymbolAddress((void**)&xh, g_xh);   cudaGetSymbolAddress((void**)&xl, g_xl);
    cudaGetSymbolAddress((void**)&ah, g_ah);   cudaGetSymbolAddress((void**)&al, g_al);
    cudaGetSymbolAddress((void**)&wqh, g_wqh); cudaGetSymbolAddress((void**)&wql, g_wql);
    cudaGetSymbolAddress((void**)&woh, g_woh); cudaGetSymbolAddress((void**)&wol, g_wol);
    cudaGetSymbolAddress((void**)&q2h, g_q2h); cudaGetSymbolAddress((void**)&q2l, g_q2l);
    cudaGetSymbolAddress((void**)&k2h, g_k2h); cudaGetSymbolAddress((void**)&k2l, g_k2l);
    cudaGetSymbolAddress((void**)&v2h, g_v2h); cudaGetSymbolAddress((void**)&v2l, g_v2l);

    const int GEMM_SMEM = 4 * 20480;
    cudaFuncSetAttribute(gemm_mma<1>, cudaFuncAttributeMaxDynamicSharedMemorySize, GEMM_SMEM);
    cudaFuncSetAttribute(gemm_mma<2>, cudaFuncAttributeMaxDynamicSharedMemorySize, GEMM_SMEM);
    cudaFuncSetAttribute(flash_mma, cudaFuncAttributeMaxDynamicSharedMemorySize, 73728);

    // 1) split x ; split+transpose w_qkv
    {
        const int n4 = MTOT * DIMM / 4;
        split_kernel<<<n4 / 256, 256>>>(x, xh, xl, n4);
        tsplit_kernel<<<dim3(NQKV / 32, DIMM / 32), 256>>>(w_qkv, wqh, wql, DIMM, NQKV);
    }
    // 2) QKV = x @ w_qkv with fused head-major hi/lo split epilogue
    gemm_mma<2><<<dim3(NQKV / 128, MTOT / 128), 256, GEMM_SMEM>>>(
        xh, xl, wqh, wql, nullptr, nullptr,
        q2h, q2l, k2h, k2l, v2h, v2l, MTOT, NQKV, DIMM);

    // 3) HMMA flash attention -> writes g_ah/g_al directly (permuted)
    flash_mma<<<dim3(SS / 128, NHEADS, BB), 128, 73728>>>(
        q2h, q2l, k2h, k2l, v2h, v2l, ah, al);

    // 4) split+transpose w_out ; out = attn @ w_out + b
    tsplit_kernel<<<dim3(DIMM / 32, DIMM / 32), 256>>>(w_out, woh, wol, DIMM, DIMM);
    gemm_mma<1><<<dim3(DIMM / 128, MTOT / 128), 256, GEMM_SMEM>>>(
        ah, al, woh, wol, b_out, out,
        nullptr, nullptr, nullptr, nullptr, nullptr, nullptr, MTOT, DIMM, DIMM);
}

// round 11
// speedup vs baseline: 3.6966x; 1.0367x over previous
#include <cuda_runtime.h>
#include <cuda_bf16.h>
#include <cstdint>
#include <cstddef>

#define DIMM   1024
#define NHEADS 16
#define HD     64
#define BB     4
#define SS     2048
#define MTOT   (BB * SS)      // 8192
#define NQKV   (3 * DIMM)     // 3072

typedef __nv_bfloat16 bf16;

// ---------------- scratch (__device__ globals; no allocation) ----------------
__device__ bf16 g_xh[(size_t)MTOT * DIMM], g_xl[(size_t)MTOT * DIMM];
__device__ bf16 g_ah[(size_t)MTOT * DIMM], g_al[(size_t)MTOT * DIMM];
__device__ bf16 g_wqh[(size_t)NQKV * DIMM], g_wql[(size_t)NQKV * DIMM]; // [N,K]
__device__ bf16 g_woh[(size_t)DIMM * DIMM], g_wol[(size_t)DIMM * DIMM]; // [N,K]
// head-major [b,h,s,d] split Q/K/V (Q pre-scaled by 0.125*log2e)
__device__ bf16 g_q2h[(size_t)MTOT * DIMM], g_q2l[(size_t)MTOT * DIMM];
__device__ bf16 g_k2h[(size_t)MTOT * DIMM], g_k2l[(size_t)MTOT * DIMM];
__device__ bf16 g_v2h[(size_t)MTOT * DIMM], g_v2l[(size_t)MTOT * DIMM];

// ---------------- helpers ----------------
__device__ __forceinline__ float ex2f(float x) {
    float r; asm("ex2.approx.ftz.f32 %0, %1;" : "=f"(r) : "f"(x)); return r;
}
__device__ __forceinline__ uint32_t s2u(const void* p) {
    uint32_t a;
    asm("{ .reg .u64 t; cvta.to.shared.u64 t, %1; cvt.u32.u64 %0, t; }" : "=r"(a) : "l"(p));
    return a;
}
__device__ __forceinline__ void mma16816(float* c, const uint32_t* a, const uint32_t* b) {
    asm volatile("mma.sync.aligned.m16n8k16.row.col.f32.bf16.bf16.f32 "
        "{%0,%1,%2,%3}, {%4,%5,%6,%7}, {%8,%9}, {%0,%1,%2,%3};"
        : "+f"(c[0]), "+f"(c[1]), "+f"(c[2]), "+f"(c[3])
        : "r"(a[0]), "r"(a[1]), "r"(a[2]), "r"(a[3]), "r"(b[0]), "r"(b[1]));
}
__device__ __forceinline__ void ldsm4(uint32_t* r, uint32_t addr) {
    asm volatile("ldmatrix.sync.aligned.m8n8.x4.shared.b16 {%0,%1,%2,%3}, [%4];"
        : "=r"(r[0]), "=r"(r[1]), "=r"(r[2]), "=r"(r[3]) : "r"(addr));
}
__device__ __forceinline__ void ldsm4t(uint32_t* r, uint32_t addr) {
    asm volatile("ldmatrix.sync.aligned.m8n8.x4.trans.shared.b16 {%0,%1,%2,%3}, [%4];"
        : "=r"(r[0]), "=r"(r[1]), "=r"(r[2]), "=r"(r[3]) : "r"(addr));
}
// pack {lo, hi} fp32 -> bf16x2 (lo in low half)
__device__ __forceinline__ uint32_t packbf(float lo, float hi) {
    uint32_t r; asm("cvt.rn.bf16x2.f32 %0, %1, %2;" : "=r"(r) : "f"(hi), "f"(lo)); return r;
}
__device__ __forceinline__ float u2f(uint32_t x) { return __uint_as_float(x); }

// ---------------------------------------------------------------------------
// Split fp32 -> (bf16 hi, bf16 lo)
// ---------------------------------------------------------------------------
__global__ __launch_bounds__(256) void split_kernel(
    const float* __restrict__ in, bf16* __restrict__ oh,
    bf16* __restrict__ ol, int n4)
{
    int i = blockIdx.x * 256 + threadIdx.x;
    if (i >= n4) return;
    float4 v = ((const float4*)in)[i];
    bf16 h0 = __float2bfloat16(v.x), h1 = __float2bfloat16(v.y);
    bf16 h2 = __float2bfloat16(v.z), h3 = __float2bfloat16(v.w);
    ((__nv_bfloat162*)oh)[2 * i]     = __nv_bfloat162(h0, h1);
    ((__nv_bfloat162*)oh)[2 * i + 1] = __nv_bfloat162(h2, h3);
    ((__nv_bfloat162*)ol)[2 * i]     = __nv_bfloat162(
        __float2bfloat16(v.x - __bfloat162float(h0)),
        __float2bfloat16(v.y - __bfloat162float(h1)));
    ((__nv_bfloat162*)ol)[2 * i + 1] = __nv_bfloat162(
        __float2bfloat16(v.z - __bfloat162float(h2)),
        __float2bfloat16(v.w - __bfloat162float(h3)));
}

// ---------------------------------------------------------------------------
// Split + transpose: fp32 [K,N] row-major -> bf16 [N,K] row-major (hi/lo)
// ---------------------------------------------------------------------------
__global__ __launch_bounds__(256) void tsplit_kernel(
    const float* __restrict__ in, bf16* __restrict__ oh,
    bf16* __restrict__ ol, int K, int N)
{
    __shared__ float tile[32][33];
    const int bn = blockIdx.x * 32, bk = blockIdx.y * 32;
    const int tx = threadIdx.x & 31, ty = threadIdx.x >> 5;
#pragma unroll
    for (int i = 0; i < 4; i++)
        tile[ty + 8 * i][tx] = in[(size_t)(bk + ty + 8 * i) * N + bn + tx];
    __syncthreads();
#pragma unroll
    for (int i = 0; i < 4; i++) {
        const int n = bn + ty + 8 * i, k = bk + tx;
        float v = tile[tx][ty + 8 * i];
        bf16 h = __float2bfloat16(v);
        oh[(size_t)n * K + k] = h;
        ol[(size_t)n * K + k] = __float2bfloat16(v - __bfloat162float(h));
    }
}

// ---------------------------------------------------------------------------
// HMMA bf16-split GEMM, K=1024 fixed. 128x128 tile, BK=64, 8 warps (2x4).
// 3-slot cp.async ring (one __syncthreads per stage), smem-staged epilogue.
// MODE 1: fp32 C + bias. MODE 2: fused head-major QKV hi/lo split epilogue.
// Dynamic smem: 3 slots x (A 18432 + B 18432) = 110592 B.
// ---------------------------------------------------------------------------
template <int MODE>
__global__ __launch_bounds__(256, 2) void gemm_mma(
    const bf16* __restrict__ Ah, const bf16* __restrict__ Al,
    const bf16* __restrict__ Bh, const bf16* __restrict__ Bl,
    const float* __restrict__ bias, float* __restrict__ C,
    bf16* __restrict__ Q2h, bf16* __restrict__ Q2l,
    bf16* __restrict__ K2h, bf16* __restrict__ K2l,
    bf16* __restrict__ V2h, bf16* __restrict__ V2l,
    int M, int N)
{
    constexpr int K = 1024;
    constexpr int KC = 16;        // 64-K chunks per region
    constexpr int St = 3 * KC;    // 48 stages
    constexpr uint32_t SLOT = 36864;

    extern __shared__ char sm[];
    const uint32_t smb = s2u(sm);
    const int tid = threadIdx.x, lane = tid & 31, wid = tid >> 5;
    const int wr = wid & 1, wc = wid >> 1;
    const int bx = blockIdx.x, by = blockIdx.y;

    float acc[4][4][4];
#pragma unroll
    for (int m = 0; m < 4; m++)
#pragma unroll
        for (int n = 0; n < 4; n++)
#pragma unroll
            for (int e = 0; e < 4; e++) acc[m][n][e] = 0.f;

    const uint32_t a_row = wr * 64 + ((lane >> 3) & 1) * 8 + (lane & 7);
    const uint32_t a_colb = (lane >> 4) * 16;
    const uint32_t b_row = wc * 32 + (lane >> 4) * 8 + (lane & 7);
    const uint32_t b_colb = ((lane >> 3) & 1) * 16;
    const uint32_t aoff = a_row * 144 + a_colb;
    const uint32_t boff = 18432 + b_row * 144 + b_colb;

#define ISSUE_LOAD(s_)                                                            \
    {                                                                             \
        const int s__ = (s_);                                                     \
        const int region = s__ >> 4;                                              \
        const int k0 = (s__ & 15) * 64;                                           \
        const bf16* Ag = (region == 1) ? Al : Ah;                                 \
        const bf16* Bg = (region == 2) ? Bl : Bh;                                 \
        const uint32_t sb = smb + (uint32_t)(s__ % 3) * SLOT;                     \
        _Pragma("unroll")                                                         \
        for (int i = 0; i < 4; i++) {                                             \
            const int chunk = tid + i * 256;                                      \
            const int row = chunk >> 3, seg = chunk & 7;                          \
            uint32_t da = sb + row * 144 + seg * 16;                              \
            const void* ga = Ag + (size_t)(by * 128 + row) * K + k0 + seg * 8;    \
            asm volatile("cp.async.cg.shared.global [%0], [%1], 16;"              \
                         :: "r"(da), "l"(ga));                                    \
            uint32_t db = sb + 18432 + row * 144 + seg * 16;                      \
            const void* gb = Bg + (size_t)(bx * 128 + row) * K + k0 + seg * 8;    \
            asm volatile("cp.async.cg.shared.global [%0], [%1], 16;"              \
                         :: "r"(db), "l"(gb));                                    \
        }                                                                         \
        asm volatile("cp.async.commit_group;" ::: "memory");                      \
    }

    ISSUE_LOAD(0); ISSUE_LOAD(1);

    for (int s = 0; s < St; s++) {
        if (s + 1 < St) asm volatile("cp.async.wait_group 1;" ::: "memory");
        else            asm volatile("cp.async.wait_group 0;" ::: "memory");
        __syncthreads();
        if (s + 2 < St) ISSUE_LOAD(s + 2);

        const uint32_t sb = smb + (uint32_t)(s % 3) * SLOT;
        const uint32_t abase = sb + aoff;
        const uint32_t bbase = sb + boff;

#pragma unroll
        for (int kk = 0; kk < 4; kk++) {
            uint32_t a[4][4], b[4][2];
#pragma unroll
            for (int m = 0; m < 4; m++)
                ldsm4(a[m], abase + m * 16 * 144 + kk * 32);
#pragma unroll
            for (int p = 0; p < 2; p++) {
                uint32_t r[4];
                ldsm4(r, bbase + p * 16 * 144 + kk * 32);
                b[2 * p][0] = r[0]; b[2 * p][1] = r[1];
                b[2 * p + 1][0] = r[2]; b[2 * p + 1][1] = r[3];
            }
#pragma unroll
            for (int m = 0; m < 4; m++)
#pragma unroll
                for (int n = 0; n < 4; n++)
                    mma16816(acc[m][n], a[m], b[n]);
        }
    }
#undef ISSUE_LOAD

    // ---- epilogue: stage C tile in smem (fp32 128x132), write coalesced ----
    __syncthreads();
    float* cs = (float*)sm;
#pragma unroll
    for (int m = 0; m < 4; m++) {
        const int r0 = wr * 64 + m * 16 + (lane >> 2);
#pragma unroll
        for (int n = 0; n < 4; n++) {
            const int c0 = wc * 32 + n * 8 + 2 * (lane & 3);
#pragma unroll
            for (int half = 0; half < 2; half++) {
                cs[(r0 + half * 8) * 132 + c0]     = acc[m][n][half * 2];
                cs[(r0 + half * 8) * 132 + c0 + 1] = acc[m][n][half * 2 + 1];
            }
        }
    }
    __syncthreads();

    if (MODE == 2) {
        const float cq = 0.125f * 1.44269504088896340736f;
        const int region = (bx * 128) >> 10;
#pragma unroll
        for (int w = 0; w < 32; w++) {
            const int task = wid + w * 8;       // 0..255
            const int r = task >> 1, hh = task & 1;
            const int grow = by * 128 + r;
            const int b_ = grow >> 11, s_ = grow & (SS - 1);
            const int head = ((bx * 128 + hh * 64) >> 6) & (NHEADS - 1);
            float vx = cs[r * 132 + hh * 64 + 2 * lane];
            float vy = cs[r * 132 + hh * 64 + 2 * lane + 1];
            if (region == 0) { vx *= cq; vy *= cq; }
            const uint32_t hp = packbf(vx, vy);
            const uint32_t lp = packbf(vx - u2f(hp << 16), vy - u2f(hp & 0xffff0000u));
            bf16* oh = (region == 0) ? Q2h : (region == 1) ? K2h : V2h;
            bf16* ol = (region == 0) ? Q2l : (region == 1) ? K2l : V2l;
            const size_t oi = ((size_t)(b_ * NHEADS + head) * SS + s_) * HD;
            ((uint32_t*)(oh + oi))[lane] = hp;
            ((uint32_t*)(ol + oi))[lane] = lp;
        }
    } else {
#pragma unroll
        for (int i = 0; i < 16; i++) {
            const int r = wid * 16 + i;
            float4 v = *(float4*)&cs[r * 132 + lane * 4];
            const int col = bx * 128 + lane * 4;
            if (MODE == 1) {
                float4 bv = *(const float4*)&bias[col];
                v.x += bv.x; v.y += bv.y; v.z += bv.z; v.w += bv.w;
            }
            *(float4*)&C[(size_t)(by * 128 + r) * N + col] = v;
        }
    }
}

// ---------------------------------------------------------------------------
// HMMA flash attention (validated round 6/7). CTA = 128 q-rows of one (b,h).
// ---------------------------------------------------------------------------
__global__ __launch_bounds__(128, 2) void flash_mma(
    const bf16* __restrict__ Qh, const bf16* __restrict__ Ql,
    const bf16* __restrict__ Kh, const bf16* __restrict__ Kl,
    const bf16* __restrict__ Vh, const bf16* __restrict__ Vl,
    bf16* __restrict__ Oh, bf16* __restrict__ Ol)
{
    extern __shared__ char sm[];
    const int tid = threadIdx.x, lane = tid & 31, wid = tid >> 5;
    const int qt = blockIdx.x, h = blockIdx.y, b = blockIdx.z;
    const size_t bh = (size_t)(b * NHEADS + h) * SS;
    const uint32_t smb = s2u(sm);

    {
        const bf16* q0 = Qh + (bh + qt * 128) * HD;
        const bf16* q1 = Ql + (bh + qt * 128) * HD;
#pragma unroll
        for (int i = 0; i < 8; i++) {
            const int c = tid + i * 128;
            const int row = c >> 3, seg = c & 7;
            uint32_t d0 = smb + row * 144 + seg * 16;
            const void* s0 = q0 + (size_t)row * HD + seg * 8;
            asm volatile("cp.async.cg.shared.global [%0], [%1], 16;" :: "r"(d0), "l"(s0));
            uint32_t d1 = smb + 18432 + row * 144 + seg * 16;
            const void* s1 = q1 + (size_t)row * HD + seg * 8;
            asm volatile("cp.async.cg.shared.global [%0], [%1], 16;" :: "r"(d1), "l"(s1));
        }
        asm volatile("cp.async.commit_group;" ::: "memory");
        asm volatile("cp.async.wait_group 0;" ::: "memory");
        __syncthreads();
    }
    uint32_t qfh[2][4][4], qfl[2][4][4];
    {
        const uint32_t arow = wid * 32 + ((lane >> 3) & 1) * 8 + (lane & 7);
        const uint32_t acolb = (lane >> 4) * 16;
#pragma unroll
        for (int m = 0; m < 2; m++)
#pragma unroll
            for (int kk = 0; kk < 4; kk++) {
                ldsm4(qfh[m][kk], smb + (arow + m * 16) * 144 + acolb + kk * 32);
                ldsm4(qfl[m][kk], smb + 18432 + (arow + m * 16) * 144 + acolb + kk * 32);
            }
    }
    __syncthreads();

    float o[2][8][4];
#pragma unroll
    for (int m = 0; m < 2; m++)
#pragma unroll
        for (int n = 0; n < 8; n++)
#pragma unroll
            for (int e = 0; e < 4; e++) o[m][n][e] = 0.f;
    float rm[2][2] = {{-1e30f, -1e30f}, {-1e30f, -1e30f}};
    float rl[2][2] = {{0.f, 0.f}, {0.f, 0.f}};

#define ISSUE_KV(t_)                                                              \
    do {                                                                          \
        const int t__ = (t_);                                                     \
        const uint32_t base_ = smb + (t__ & 1) * 36864;                           \
        const size_t off_ = (bh + (size_t)t__ * 64) * HD;                         \
        const bf16* sA[4] = {Kh + off_, Kl + off_, Vh + off_, Vl + off_};         \
        _Pragma("unroll")                                                         \
        for (int a = 0; a < 4; a++) {                                             \
            _Pragma("unroll")                                                     \
            for (int i = 0; i < 4; i++) {                                         \
                const int c = tid + i * 128;                                      \
                const int row = c >> 3, seg = c & 7;                              \
                uint32_t dst = base_ + a * 9216 + row * 144 + seg * 16;           \
                const void* src = sA[a] + (size_t)row * HD + seg * 8;             \
                asm volatile("cp.async.cg.shared.global [%0], [%1], 16;"          \
                             :: "r"(dst), "l"(src));                              \
            }                                                                     \
        }                                                                         \
        asm volatile("cp.async.commit_group;" ::: "memory");                      \
    } while (0)

    ISSUE_KV(0);

    const uint32_t brow = (lane >> 4) * 8 + (lane & 7);
    const uint32_t bcolb = ((lane >> 3) & 1) * 16;
    const uint32_t vrowi = ((lane >> 3) & 1) * 8 + (lane & 7);
    const uint32_t vcoli = (lane >> 4);

    for (int t = 0; t < 32; t++) {
        if (t + 1 < 32) {
            ISSUE_KV(t + 1);
            asm volatile("cp.async.wait_group 1;" ::: "memory");
        } else {
            asm volatile("cp.async.wait_group 0;" ::: "memory");
        }
        __syncthreads();

        const uint32_t base = smb + (t & 1) * 36864;
        const uint32_t KHb = base, KLb = base + 9216;
        const uint32_t VHb = base + 18432, VLb = base + 27648;

        float s[2][8][4];
#pragma unroll
        for (int m = 0; m < 2; m++)
#pragma unroll
            for (int n = 0; n < 8; n++)
#pragma unroll
                for (int e = 0; e < 4; e++) s[m][n][e] = 0.f;

#pragma unroll
        for (int kk = 0; kk < 4; kk++) {
            uint32_t kb[8][2];
#pragma unroll
            for (int p = 0; p < 4; p++) {
                uint32_t r[4];
                ldsm4(r, KHb + (p * 16 + brow) * 144 + bcolb + kk * 32);
                kb[2 * p][0] = r[0]; kb[2 * p][1] = r[1];
                kb[2 * p + 1][0] = r[2]; kb[2 * p + 1][1] = r[3];
            }
#pragma unroll
            for (int m = 0; m < 2; m++)
#pragma unroll
                for (int n = 0; n < 8; n++) {
                    mma16816(s[m][n], qfh[m][kk], kb[n]);
                    mma16816(s[m][n], qfl[m][kk], kb[n]);
                }
#pragma unroll
            for (int p = 0; p < 4; p++) {
                uint32_t r[4];
                ldsm4(r, KLb + (p * 16 + brow) * 144 + bcolb + kk * 32);
                kb[2 * p][0] = r[0]; kb[2 * p][1] = r[1];
                kb[2 * p + 1][0] = r[2]; kb[2 * p + 1][1] = r[3];
            }
#pragma unroll
            for (int m = 0; m < 2; m++)
#pragma unroll
                for (int n = 0; n < 8; n++)
                    mma16816(s[m][n], qfh[m][kk], kb[n]);
        }

#pragma unroll
        for (int m = 0; m < 2; m++)
#pragma unroll
            for (int eh = 0; eh < 2; eh++) {
                float mx = -1e30f;
#pragma unroll
                for (int n = 0; n < 8; n++) {
                    mx = fmaxf(mx, s[m][n][eh * 2]);
                    mx = fmaxf(mx, s[m][n][eh * 2 + 1]);
                }
                mx = fmaxf(mx, __shfl_xor_sync(0xffffffffu, mx, 1));
                mx = fmaxf(mx, __shfl_xor_sync(0xffffffffu, mx, 2));
                const float newm = fmaxf(rm[m][eh], mx);
                const float corr = ex2f(rm[m][eh] - newm);
                rm[m][eh] = newm;
                float sum = 0.f;
#pragma unroll
                for (int n = 0; n < 8; n++) {
                    float p0 = ex2f(s[m][n][eh * 2] - newm);
                    float p1 = ex2f(s[m][n][eh * 2 + 1] - newm);
                    s[m][n][eh * 2] = p0; s[m][n][eh * 2 + 1] = p1;
                    sum += p0 + p1;
                }
                sum += __shfl_xor_sync(0xffffffffu, sum, 1);
                sum += __shfl_xor_sync(0xffffffffu, sum, 2);
                rl[m][eh] = rl[m][eh] * corr + sum;
#pragma unroll
                for (int n = 0; n < 8; n++) {
                    o[m][n][eh * 2] *= corr;
                    o[m][n][eh * 2 + 1] *= corr;
                }
            }

#pragma unroll
        for (int kk = 0; kk < 4; kk++) {
            uint32_t ph[2][4], pl[2][4];
#pragma unroll
            for (int m = 0; m < 2; m++)
#pragma unroll
                for (int half = 0; half < 2; half++)
#pragma unroll
                    for (int eh = 0; eh < 2; eh++) {
                        const float p0 = s[m][2 * kk + half][eh * 2];
                        const float p1 = s[m][2 * kk + half][eh * 2 + 1];
                        const uint32_t hp = packbf(p0, p1);
                        const float h0 = u2f(hp << 16), h1 = u2f(hp & 0xffff0000u);
                        ph[m][half * 2 + eh] = hp;
                        pl[m][half * 2 + eh] = packbf(p0 - h0, p1 - h1);
                    }

            uint32_t vb[8][2];
#pragma unroll
            for (int g = 0; g < 4; g++) {
                uint32_t r[4];
                ldsm4t(r, VHb + (kk * 16 + vrowi) * 144 + (g * 2 + vcoli) * 16);
                vb[2 * g][0] = r[0]; vb[2 * g][1] = r[1];
                vb[2 * g + 1][0] = r[2]; vb[2 * g + 1][1] = r[3];
            }
#pragma unroll
            for (int m = 0; m < 2; m++)
#pragma unroll
                for (int n = 0; n < 8; n++) {
                    mma16816(o[m][n], ph[m], vb[n]);
                    mma16816(o[m][n], pl[m], vb[n]);
                }
#pragma unroll
            for (int g = 0; g < 4; g++) {
                uint32_t r[4];
                ldsm4t(r, VLb + (kk * 16 + vrowi) * 144 + (g * 2 + vcoli) * 16);
                vb[2 * g][0] = r[0]; vb[2 * g][1] = r[1];
                vb[2 * g + 1][0] = r[2]; vb[2 * g + 1][1] = r[3];
            }
#pragma unroll
            for (int m = 0; m < 2; m++)
#pragma unroll
                for (int n = 0; n < 8; n++)
                    mma16816(o[m][n], ph[m], vb[n]);
        }
        __syncthreads();
    }
#undef ISSUE_KV

#pragma unroll
    for (int m = 0; m < 2; m++)
#pragma unroll
        for (int eh = 0; eh < 2; eh++) {
            const float inv = 1.f / rl[m][eh];
            const int gs = qt * 128 + wid * 32 + m * 16 + (lane >> 2) + eh * 8;
            const size_t rowbase =
                ((size_t)(b * SS) + h * 128 + (gs >> 4)) * DIMM + (gs & 15) * HD;
#pragma unroll
            for (int n = 0; n < 8; n++) {
                const int d = n * 8 + 2 * (lane & 3);
                const float p0 = o[m][n][eh * 2] * inv;
                const float p1 = o[m][n][eh * 2 + 1] * inv;
                const uint32_t hp = packbf(p0, p1);
                const float h0 = u2f(hp << 16), h1 = u2f(hp & 0xffff0000u);
                const uint32_t lp = packbf(p0 - h0, p1 - h1);
                *(uint32_t*)(Oh + rowbase + d) = hp;
                *(uint32_t*)(Ol + rowbase + d) = lp;
            }
        }
}

// ---------------------------------------------------------------------------
// Launch
// ---------------------------------------------------------------------------
extern "C" void kernel_launch(void* const* d_in, const int* in_sizes, int n_in,
                              void* d_out, int out_size)
{
    const float* x     = (const float*)d_in[0];
    const float* w_qkv = (const float*)d_in[1];   // [1024,3072] = [K,N]
    const float* w_out = (const float*)d_in[2];   // [1024,1024]
    const float* b_out = (const float*)d_in[3];
    float* out = (float*)d_out;

    bf16 *xh, *xl, *ah, *al, *wqh, *wql, *woh, *wol;
    bf16 *q2h, *q2l, *k2h, *k2l, *v2h, *v2l;
    cudaGetSymbolAddress((void**)&xh, g_xh);   cudaGetSymbolAddress((void**)&xl, g_xl);
    cudaGetSymbolAddress((void**)&ah, g_ah);   cudaGetSymbolAddress((void**)&al, g_al);
    cudaGetSymbolAddress((void**)&wqh, g_wqh); cudaGetSymbolAddress((void**)&wql, g_wql);
    cudaGetSymbolAddress((void**)&woh, g_woh); cudaGetSymbolAddress((void**)&wol, g_wol);
    cudaGetSymbolAddress((void**)&q2h, g_q2h); cudaGetSymbolAddress((void**)&q2l, g_q2l);
    cudaGetSymbolAddress((void**)&k2h, g_k2h); cudaGetSymbolAddress((void**)&k2l, g_k2l);
    cudaGetSymbolAddress((void**)&v2h, g_v2h); cudaGetSymbolAddress((void**)&v2l, g_v2l);

    const int GEMM_SMEM = 3 * 36864;   // 110592
    cudaFuncSetAttribute(gemm_mma<1>, cudaFuncAttributeMaxDynamicSharedMemorySize, GEMM_SMEM);
    cudaFuncSetAttribute(gemm_mma<2>, cudaFuncAttributeMaxDynamicSharedMemorySize, GEMM_SMEM);
    cudaFuncSetAttribute(flash_mma, cudaFuncAttributeMaxDynamicSharedMemorySize, 73728);

    // 1) split x ; split+transpose w_qkv
    {
        const int n4 = MTOT * DIMM / 4;
        split_kernel<<<n4 / 256, 256>>>(x, xh, xl, n4);
        tsplit_kernel<<<dim3(NQKV / 32, DIMM / 32), 256>>>(w_qkv, wqh, wql, DIMM, NQKV);
    }
    // 2) QKV = x @ w_qkv with fused head-major hi/lo split epilogue
    gemm_mma<2><<<dim3(NQKV / 128, MTOT / 128), 256, GEMM_SMEM>>>(
        xh, xl, wqh, wql, nullptr, nullptr,
        q2h, q2l, k2h, k2l, v2h, v2l, MTOT, NQKV);

    // 3) HMMA flash attention -> writes g_ah/g_al directly (permuted)
    flash_mma<<<dim3(SS / 128, NHEADS, BB), 128, 73728>>>(
        q2h, q2l, k2h, k2l, v2h, v2l, ah, al);

    // 4) split+transpose w_out ; out = attn @ w_out + b
    tsplit_kernel<<<dim3(DIMM / 32, DIMM / 32), 256>>>(w_out, woh, wol, DIMM, DIMM);
    gemm_mma<1><<<dim3(DIMM / 128, MTOT / 128), 256, GEMM_SMEM>>>(
        ah, al, woh, wol, b_out, out,
        nullptr, nullptr, nullptr, nullptr, nullptr, nullptr, MTOT, DIMM);
}